// round 10
// baseline (speedup 1.0000x reference)
#include <cuda_runtime.h>
#include <cuda_fp16.h>
#include <math.h>
#include <stdint.h>

// Problem constants
#define BB   2
#define LL   4096
#define DIMD 1024
#define NH   16
#define HD   64
#define MROWS (BB * LL)          // 8192
#define KDIM 1024
#define CHUNK  64
#define NCHUNK (LL / CHUNK)      // 64
#define NCID   (BB * NH * NCHUNK) // 2048
#define NPJ  6144                // fused projection width

// ---------------------------------------------------------------------------
// Scratch
// ---------------------------------------------------------------------------
__device__ float g_xp[(size_t)MROWS * 2048];
__device__ float g_pj[(size_t)MROWS * NPJ];   // q|k|v|i|f|o fused, ld=6144
// fp16 split operand buffers
__device__ __half g_xh [(size_t)MROWS * 1024];
__device__ __half g_xl [(size_t)MROWS * 1024];
__device__ __half g_xph[(size_t)MROWS * 2048];
__device__ __half g_xpl[(size_t)MROWS * 2048];
__device__ __half g_hh [(size_t)MROWS * 1024];
__device__ __half g_hl [(size_t)MROWS * 1024];
__device__ __half g_wif[(size_t)2048 * 1024];
__device__ __half g_w6f[(size_t)6 * 1024 * 1024];
__device__ __half g_wof[(size_t)1024 * 1024];
// chunked-scan scratch
__device__ float g_dC [(size_t)NCID * 4096];
__device__ float g_dN [(size_t)NCID * 64];
__device__ float g_G  [(size_t)NCID * 64];
__device__ float g_Cst[(size_t)NCID * 4096];
__device__ float g_Nst[(size_t)NCID * 64];

// ---------------------------------------------------------------------------
// helpers
// ---------------------------------------------------------------------------
__device__ __forceinline__ uint32_t packh(float x, float y) {
    __half hx = __float2half_rn(x);
    __half hy = __float2half_rn(y);
    return (uint32_t)__half_as_ushort(hx) | ((uint32_t)__half_as_ushort(hy) << 16);
}
__device__ __forceinline__ uint32_t packhl(float x, float y) {
    __half hx = __float2half_rn(x);
    __half hy = __float2half_rn(y);
    return packh(x - __half2float(hx), y - __half2float(hy));
}
__device__ __forceinline__ void cp16(uint32_t s, const void* g)
{
    asm volatile("cp.async.ca.shared.global [%0], [%1], 16;\n" :: "r"(s), "l"(g));
}

#define LDSM_X4(r0, r1, r2, r3, addr) \
    asm volatile("ldmatrix.sync.aligned.m8n8.x4.shared.b16 {%0,%1,%2,%3}, [%4];" \
                 : "=r"(r0), "=r"(r1), "=r"(r2), "=r"(r3) : "r"(addr))

// fp32-accumulator MMA (hi term)
#define MMA_F16(d, a, b0, b1) \
    asm volatile("mma.sync.aligned.m16n8k16.row.col.f32.f16.f16.f32 " \
                 "{%0,%1,%2,%3}, {%4,%5,%6,%7}, {%8,%9}, {%0,%1,%2,%3};" \
                 : "+f"((d)[0]), "+f"((d)[1]), "+f"((d)[2]), "+f"((d)[3]) \
                 : "r"((a)[0]), "r"((a)[1]), "r"((a)[2]), "r"((a)[3]), \
                   "r"(b0), "r"(b1))

// fp16-accumulator MMA (lo term; dl = 2 packed f16x2 regs)
#define MMA_F16A16(dl, a, b0, b1) \
    asm volatile("mma.sync.aligned.m16n8k16.row.col.f16.f16.f16.f16 " \
                 "{%0,%1}, {%2,%3,%4,%5}, {%6,%7}, {%0,%1};" \
                 : "+r"((dl)[0]), "+r"((dl)[1]) \
                 : "r"((a)[0]), "r"((a)[1]), "r"((a)[2]), "r"((a)[3]), \
                   "r"(b0), "r"(b1))

// ---------------------------------------------------------------------------
// Pass 0a: fp32 -> (hi, lo) fp16 split (for x)
// ---------------------------------------------------------------------------
__global__ void split_h(const float4* __restrict__ s, uint2* __restrict__ hi,
                        uint2* __restrict__ lo, int n4)
{
    int i = blockIdx.x * 256 + threadIdx.x;
    if (i >= n4) return;
    float4 v = s[i];
    uint2 h, l;
    h.x = packh(v.x, v.y);  h.y = packh(v.z, v.w);
    l.x = packhl(v.x, v.y); l.y = packhl(v.z, v.w);
    hi[i] = h; lo[i] = l;
}

// Pass 0b: fp32 -> fp16 (single matrix)
__global__ void cvt_h(const float4* __restrict__ s, uint2* __restrict__ d, int n4)
{
    int i = blockIdx.x * 256 + threadIdx.x;
    if (i >= n4) return;
    float4 v = s[i];
    uint2 o;
    o.x = packh(v.x, v.y); o.y = packh(v.z, v.w);
    d[i] = o;
}

// Pass 0c: fp32 -> fp16 for the 6 projection weights in one launch.
__global__ void cvt_h6(const float4* __restrict__ s0, const float4* __restrict__ s1,
                       const float4* __restrict__ s2, const float4* __restrict__ s3,
                       const float4* __restrict__ s4, const float4* __restrict__ s5,
                       uint2* __restrict__ d)
{
    const int n4 = 1024 * 1024 / 4;
    int i = blockIdx.x * 256 + threadIdx.x;
    if (i >= n4) return;
    const float4* s;
    switch (blockIdx.y) {
        case 0: s = s0; break; case 1: s = s1; break; case 2: s = s2; break;
        case 3: s = s3; break; case 4: s = s4; break; default: s = s5; break;
    }
    float4 v = s[i];
    uint2 o;
    o.x = packh(v.x, v.y); o.y = packh(v.z, v.w);
    d[(size_t)blockIdx.y * n4 + i] = o;
}

// ---------------------------------------------------------------------------
// cp.async pipelined fp16 mixed-accumulator GEMM.
// C[M,N] = (Ah+Al)[M,K] @ B[N,K]^T, K=1024, CTA 128x128, warp 64x64, BK=32.
// R10: hi term (Ah*B) -> fp32 accumulators; lo term (Al*B) -> fp16
// accumulators (half-rate pipe hypothesis); merged in epilogue.
// A-fragment registers are reused between the hi and lo phases to fit regs.
// MODE 0: in_proj -> fp32 C + fp16 hi/lo split outputs
// MODE 1: fused projections, N=6144, per-1024-col-segment epilogue
// MODE 2: plain fp32 C
// ---------------------------------------------------------------------------
#define STAGES 4
#define SECB   8192
#define STAGEB (3 * SECB)             // 24576
#define GEMM_SMEM (STAGES * STAGEB)   // 98304

template <int MODE>
__global__ void __launch_bounds__(128, 2)
gemm_f16(const __half* __restrict__ Ah, const __half* __restrict__ Al, int lda,
         const __half* __restrict__ B,
         const float* __restrict__ q0, const float* __restrict__ q1,
         const float* __restrict__ q2, const float* __restrict__ q3,
         const float* __restrict__ q4,
         float* __restrict__ C, int ldc,
         __half* __restrict__ Chh, __half* __restrict__ Cll)
{
    extern __shared__ __align__(128) char smem[];
    const uint32_t sbase = (uint32_t)__cvta_generic_to_shared(smem);

    const int tid  = threadIdx.x;
    const int w    = tid >> 5;
    const int lane = tid & 31;
    const int wm   = w & 1;          // M half (64 rows)
    const int wn   = w >> 1;         // N half (64 cols)

    const int m0 = blockIdx.y * 128;
    const int n0 = blockIdx.x * 128;

    const __half* Ahp = Ah + (size_t)m0 * lda;
    const __half* Alp = Al + (size_t)m0 * lda;
    const __half* Bp  = B  + (size_t)n0 * KDIM;

    // loader: 1536 16B chunks / stage, 12 per thread
    auto load_stage = [&](int buf, int k0) {
        const uint32_t db = sbase + (uint32_t)(buf * STAGEB);
#pragma unroll
        for (int i = 0; i < 12; i++) {
            const int ci  = tid + i * 128;
            const int sec = ci >> 9;          // 0=Ah 1=Al 2=B
            const int r   = (ci >> 2) & 127;
            const int kq  = ci & 3;
            const __half* gp;
            if      (sec == 0) gp = Ahp + (size_t)r * lda;
            else if (sec == 1) gp = Alp + (size_t)r * lda;
            else               gp = Bp  + (size_t)r * KDIM;
            gp += k0 + kq * 8;
            const uint32_t d = db + (uint32_t)(sec * SECB + r * 64 + ((kq * 16) ^ ((r * 8) & 0x30)));
            cp16(d, gp);
        }
    };

    // ldmatrix per-lane addressing (SW64)
    const int a_r  = (lane & 7) + ((lane >> 3) & 1) * 8;
    const int ak2  = ((lane >> 4) & 1) * 16;
    const uint32_t axr = (uint32_t)((a_r << 3) & 0x30);
    const int g    = lane >> 3;
    const int b_r  = ((g >> 1) * 8) + (lane & 7);
    const int bk2  = (g & 1) * 16;
    const uint32_t bxr = (uint32_t)((b_r << 3) & 0x30);

    uint32_t aoff[4], boff[4];
#pragma unroll
    for (int mi = 0; mi < 4; mi++) aoff[mi] = (uint32_t)((wm * 64 + mi * 16 + a_r) * 64);
#pragma unroll
    for (int gi = 0; gi < 4; gi++) boff[gi] = (uint32_t)(2 * SECB + (wn * 64 + gi * 16 + b_r) * 64);

    float    acc [4][8][4] = {};    // hi term, fp32
    uint32_t accL[4][8][2] = {};    // lo term, packed fp16x2 (0 == +0h,+0h)

    load_stage(0, 0);
    asm volatile("cp.async.commit_group;\n");
    load_stage(1, 32);
    asm volatile("cp.async.commit_group;\n");
    load_stage(2, 64);
    asm volatile("cp.async.commit_group;\n");

    const int S = KDIM / 32;   // 32
    for (int s = 0; s < S; s++) {
        asm volatile("cp.async.wait_group 2;\n" ::: "memory");
        __syncthreads();
        if (s + 3 < S) load_stage((s + 3) & (STAGES - 1), (s + 3) * 32);
        asm volatile("cp.async.commit_group;\n");

        const uint32_t bb = sbase + (uint32_t)((s & (STAGES - 1)) * STAGEB);
#pragma unroll
        for (int kb = 0; kb < 2; kb++) {
            const uint32_t kx = (uint32_t)(kb * 32);
            // B fragments for all 4 gi (held across hi and lo phases)
            uint32_t Bf[4][4];
#pragma unroll
            for (int gi = 0; gi < 4; gi++) {
                const uint32_t ba = bb + boff[gi] + ((kx + bk2) ^ bxr);
                LDSM_X4(Bf[gi][0], Bf[gi][1], Bf[gi][2], Bf[gi][3], ba);
            }
            // phase 1: hi term (Ah), fp32 accumulators
            {
                uint32_t Af[4][4];
#pragma unroll
                for (int mi = 0; mi < 4; mi++) {
                    const uint32_t aa = bb + aoff[mi] + ((kx + ak2) ^ axr);
                    LDSM_X4(Af[mi][0], Af[mi][1], Af[mi][2], Af[mi][3], aa);
                }
#pragma unroll
                for (int gi = 0; gi < 4; gi++)
#pragma unroll
                    for (int mi = 0; mi < 4; mi++)
#pragma unroll
                        for (int hf = 0; hf < 2; hf++)
                            MMA_F16(acc[mi][gi * 2 + hf], Af[mi], Bf[gi][2 * hf], Bf[gi][2 * hf + 1]);
            }
            // phase 2: lo term (Al), fp16 accumulators
            {
                uint32_t Af[4][4];
#pragma unroll
                for (int mi = 0; mi < 4; mi++) {
                    const uint32_t aa = bb + aoff[mi] + ((kx + ak2) ^ axr) + SECB;
                    LDSM_X4(Af[mi][0], Af[mi][1], Af[mi][2], Af[mi][3], aa);
                }
#pragma unroll
                for (int gi = 0; gi < 4; gi++)
#pragma unroll
                    for (int mi = 0; mi < 4; mi++)
#pragma unroll
                        for (int hf = 0; hf < 2; hf++)
                            MMA_F16A16(accL[mi][gi * 2 + hf], Af[mi], Bf[gi][2 * hf], Bf[gi][2 * hf + 1]);
            }
        }
    }

    // merge lo-term fp16 accumulators into fp32
#pragma unroll
    for (int mi = 0; mi < 4; mi++)
#pragma unroll
        for (int ti = 0; ti < 8; ti++) {
            __half2 p0 = *reinterpret_cast<__half2*>(&accL[mi][ti][0]);
            __half2 p1 = *reinterpret_cast<__half2*>(&accL[mi][ti][1]);
            acc[mi][ti][0] += __half2float(p0.x);
            acc[mi][ti][1] += __half2float(p0.y);
            acc[mi][ti][2] += __half2float(p1.x);
            acc[mi][ti][3] += __half2float(p1.y);
        }

    const int qr = lane >> 2;
    const int qc = (lane & 3) * 2;
    const int seg = blockIdx.x >> 3;   // MODE 1: 1024-col segment

    // MODE 1 seg 0/1: fused per-head RMSNorm (warp col range = one 64-dim head)
    if (MODE == 1 && seg < 2) {
        const float* wn_ = (seg == 0) ? q0 : q1;
#pragma unroll
        for (int mi = 0; mi < 4; mi++)
#pragma unroll
            for (int rh = 0; rh < 2; rh++) {
                float ss = 0.0f;
#pragma unroll
                for (int ti = 0; ti < 8; ti++) {
                    float a = acc[mi][ti][2 * rh], b2 = acc[mi][ti][2 * rh + 1];
                    ss += a * a + b2 * b2;
                }
                ss += __shfl_xor_sync(0xffffffffu, ss, 1);
                ss += __shfl_xor_sync(0xffffffffu, ss, 2);
                const float sc = rsqrtf(ss * (1.0f / 64.0f) + 1e-6f);
#pragma unroll
                for (int ti = 0; ti < 8; ti++) {
                    acc[mi][ti][2 * rh]     *= sc * wn_[ti * 8 + qc];
                    acc[mi][ti][2 * rh + 1] *= sc * wn_[ti * 8 + qc + 1];
                }
            }
    }

#pragma unroll
    for (int mi = 0; mi < 4; mi++) {
#pragma unroll
        for (int ti = 0; ti < 8; ti++) {
            const int col = n0 + wn * 64 + ti * 8 + qc;
            float b0 = 0.f, b1 = 0.f;
            if (MODE == 1 && seg >= 3) {
                const float* bp = (seg == 3) ? q2 : (seg == 4) ? q3 : q4;
                const int cs = col & 1023;
                b0 = bp[cs]; b1 = bp[cs + 1];
            }
#pragma unroll
            for (int rh = 0; rh < 2; rh++) {
                const int row = m0 + wm * 64 + mi * 16 + rh * 8 + qr;
                float x0 = acc[mi][ti][2 * rh + 0];
                float x1 = acc[mi][ti][2 * rh + 1];
                if (MODE == 1) {
                    if (seg == 3)      { x0 = expf(x0 + b0); x1 = expf(x1 + b1); }
                    else if (seg >= 4) { x0 = 1.0f / (1.0f + expf(-(x0 + b0)));
                                         x1 = 1.0f / (1.0f + expf(-(x1 + b1))); }
                }
                *(float2*)&C[(size_t)row * ldc + col] = make_float2(x0, x1);
                if (MODE == 0) {
                    *(uint32_t*)&Chh[(size_t)row * ldc + col] = packh(x0, x1);
                    *(uint32_t*)&Cll[(size_t)row * ldc + col] = packhl(x0, x1);
                }
            }
        }
    }
}

// ---------------------------------------------------------------------------
// Chunk-parallel mLSTM scan (unchanged from R9)
// ---------------------------------------------------------------------------
__global__ void __launch_bounds__(128, 4)
chunk_fwd(const float* __restrict__ pj,
          float* __restrict__ dC, float* __restrict__ dN, float* __restrict__ G)
{
    __shared__ float stage[2][4][64];

    const int tid = threadIdx.x;
    const int cid = blockIdx.x;
    const int j   = cid & (NCHUNK - 1);
    const int bh  = cid >> 6;
    const int b   = bh >> 4;
    const int h   = bh & 15;
    const size_t base6 = ((size_t)b * LL + (size_t)j * CHUNK) * NPJ + (size_t)h * 64;

    const float* srcs[4] = { pj + base6 + 1024, pj + base6 + 2048,
                             pj + base6 + 3072, pj + base6 + 4096 };
    const int  arr = tid >> 4;
    const int  ch  = tid & 15;
    const bool loader = (tid < 64);
    const float* mySrc = srcs[loader ? arr : 0] + ch * 4;
    const uint32_t mydst0 = (uint32_t)__cvta_generic_to_shared(&stage[0][0][0]) + (arr * 64 + ch * 4) * 4;
    const uint32_t mydst1 = mydst0 + 4 * 64 * 4;

    if (loader) cp16(mydst0, mySrc);
    asm volatile("cp.async.commit_group;\n");

    const int r = tid >> 5;
    const int c = tid & 31;
    float C0[16], C1[16];
#pragma unroll
    for (int i = 0; i < 16; i++) { C0[i] = 0.0f; C1[i] = 0.0f; }
    float nreg = 0.0f, greg = 1.0f;

    for (int t = 0; t < CHUNK; t++) {
        asm volatile("cp.async.wait_group 0;\n" ::: "memory");
        __syncthreads();
        const int cur = t & 1;

        if (t + 1 < CHUNK && loader)
            cp16(cur ? mydst0 : mydst1, mySrc + (size_t)(t + 1) * NPJ);
        asm volatile("cp.async.commit_group;\n");

        const float* S   = &stage[cur][0][0];
        const float* ks  = S;
        const float* vs  = S + 64;
        const float* is_ = S + 128;
        const float* fs  = S + 192;

        float v0 = vs[c], v1 = vs[c + 32];

#pragma unroll
        for (int dd = 0; dd < 16; dd += 4) {
            int d = r * 16 + dd;
            float4 f4 = *(const float4*)&fs[d];
            float4 i4 = *(const float4*)&is_[d];
            float4 k4 = *(const float4*)&ks[d];
            float a0 = i4.x * k4.x, a1 = i4.y * k4.y, a2 = i4.z * k4.z, a3 = i4.w * k4.w;
            C0[dd+0] = fmaf(f4.x, C0[dd+0], a0 * v0); C1[dd+0] = fmaf(f4.x, C1[dd+0], a0 * v1);
            C0[dd+1] = fmaf(f4.y, C0[dd+1], a1 * v0); C1[dd+1] = fmaf(f4.y, C1[dd+1], a1 * v1);
            C0[dd+2] = fmaf(f4.z, C0[dd+2], a2 * v0); C1[dd+2] = fmaf(f4.z, C1[dd+2], a2 * v1);
            C0[dd+3] = fmaf(f4.w, C0[dd+3], a3 * v0); C1[dd+3] = fmaf(f4.w, C1[dd+3], a3 * v1);
        }

        if (tid < 64) {
            float ft = fs[tid];
            nreg = fmaf(ft, nreg, is_[tid] * ks[tid]);
            greg *= ft;
        }
        __syncthreads();
    }

    float* dCp = dC + (size_t)cid * 4096;
#pragma unroll
    for (int dd = 0; dd < 16; dd++) {
        dCp[(r * 16 + dd) * 64 + c]      = C0[dd];
        dCp[(r * 16 + dd) * 64 + c + 32] = C1[dd];
    }
    if (tid < 64) {
        dN[(size_t)cid * 64 + tid] = nreg;
        G [(size_t)cid * 64 + tid] = greg;
    }
}

__global__ void __launch_bounds__(128, 1)
chunk_carry(const float* __restrict__ dC, const float* __restrict__ dN,
            const float* __restrict__ G,
            float* __restrict__ Cst, float* __restrict__ Nst)
{
    __shared__ float gs[64], dns[64];
    const int tid = threadIdx.x;
    const int bh  = blockIdx.x;
    const int r = tid >> 5;
    const int c = tid & 31;

    float C0[16], C1[16];
#pragma unroll
    for (int i = 0; i < 16; i++) { C0[i] = 0.0f; C1[i] = 0.0f; }
    float n = 0.0f;

    for (int j = 0; j < NCHUNK; j++) {
        const size_t cid = (size_t)bh * NCHUNK + j;
        float* Cp = Cst + cid * 4096;
        const float* Dp = dC + cid * 4096;

        if (tid < 64) {
            Nst[cid * 64 + tid] = n;
            gs[tid]  = G [cid * 64 + tid];
            dns[tid] = dN[cid * 64 + tid];
        }
#pragma unroll
        for (int dd = 0; dd < 16; dd++) {
            Cp[(r * 16 + dd) * 64 + c]      = C0[dd];
            Cp[(r * 16 + dd) * 64 + c + 32] = C1[dd];
        }
        __syncthreads();
#pragma unroll
        for (int dd = 0; dd < 16; dd++) {
            float gd = gs[r * 16 + dd];
            C0[dd] = fmaf(gd, C0[dd], Dp[(r * 16 + dd) * 64 + c]);
            C1[dd] = fmaf(gd, C1[dd], Dp[(r * 16 + dd) * 64 + c + 32]);
        }
        if (tid < 64) n = fmaf(gs[tid], n, dns[tid]);
        __syncthreads();
    }
}

__global__ void __launch_bounds__(128, 4)
chunk_out(const float* __restrict__ pj, const float* __restrict__ xp,
          const float* __restrict__ Cst, const float* __restrict__ Nst,
          __half* __restrict__ hh, __half* __restrict__ hl)
{
    __shared__ float stage[2][7][64];
    __shared__ float red[4][64];
    __shared__ float denp[2];

    const int tid = threadIdx.x;
    const int cid = blockIdx.x;
    const int j   = cid & (NCHUNK - 1);
    const int bh  = cid >> 6;
    const int b   = bh >> 4;
    const int h   = bh & 15;
    const size_t base6 = ((size_t)b * LL + (size_t)j * CHUNK) * NPJ + (size_t)h * 64;
    const size_t base1 = ((size_t)b * LL + (size_t)j * CHUNK) * 1024 + (size_t)h * 64;
    const size_t baseg = ((size_t)b * LL + (size_t)j * CHUNK) * 2048 + 1024 + (size_t)h * 64;

    const float* srcs[8] = { pj + base6,        pj + base6 + 1024, pj + base6 + 2048,
                             pj + base6 + 3072, pj + base6 + 4096, pj + base6 + 5120,
                             xp + baseg,        pj + base6 };

    const int  arr = tid >> 4;
    const int  ch  = tid & 15;
    const bool loader = (tid < 112);
    const float* mySrc    = srcs[arr] + ch * 4;
    const size_t mystride = (arr == 6) ? 2048 : NPJ;
    const uint32_t mydst0 = (uint32_t)__cvta_generic_to_shared(&stage[0][0][0]) + (arr * 64 + ch * 4) * 4;
    const uint32_t mydst1 = mydst0 + 7 * 64 * 4;

    if (loader) cp16(mydst0, mySrc);
    asm volatile("cp.async.commit_group;\n");

    const int r = tid >> 5;
    const int c = tid & 31;

    const float* Cp = Cst + (size_t)cid * 4096;
    float C0[16], C1[16];
#pragma unroll
    for (int dd = 0; dd < 16; dd++) {
        C0[dd] = Cp[(r * 16 + dd) * 64 + c];
        C1[dd] = Cp[(r * 16 + dd) * 64 + c + 32];
    }
    float nreg = (tid < 64) ? Nst[(size_t)cid * 64 + tid] : 0.0f;

    for (int t = 0; t < CHUNK; t++) {
        asm volatile("cp.async.wait_group 0;\n" ::: "memory");
        __syncthreads();
        const int cur = t & 1;

        if (t + 1 < CHUNK && loader)
            cp16(cur ? mydst0 : mydst1, mySrc + (size_t)(t + 1) * mystride);
        asm volatile("cp.async.commit_group;\n");

        const float* S   = &stage[cur][0][0];
        const float* qs  = S;
        const float* ks  = S + 64;
        const float* vs  = S + 128;
        const float* is_ = S + 192;
        const float* fs  = S + 256;
        const float* ogs = S + 320;
        const float* xgs = S + 384;

        float v0 = vs[c], v1 = vs[c + 32];
        float pn0 = 0.0f, pn1 = 0.0f;

#define ROWOP(ff, qq, aa, idx) { float _a = (aa);                              \
        C0[idx] = fmaf((ff), C0[idx], _a * v0); pn0 = fmaf((qq), C0[idx], pn0);\
        C1[idx] = fmaf((ff), C1[idx], _a * v1); pn1 = fmaf((qq), C1[idx], pn1); }

#pragma unroll
        for (int dd = 0; dd < 16; dd += 4) {
            int d = r * 16 + dd;
            float4 f4 = *(const float4*)&fs[d];
            float4 q4 = *(const float4*)&qs[d];
            float4 i4 = *(const float4*)&is_[d];
            float4 k4 = *(const float4*)&ks[d];
            ROWOP(f4.x, q4.x, i4.x * k4.x, dd + 0);
            ROWOP(f4.y, q4.y, i4.y * k4.y, dd + 1);
            ROWOP(f4.z, q4.z, i4.z * k4.z, dd + 2);
            ROWOP(f4.w, q4.w, i4.w * k4.w, dd + 3);
        }
#undef ROWOP

        red[r][c]      = pn0;
        red[r][c + 32] = pn1;

        if (tid < 64) {
            float a = is_[tid] * ks[tid];
            nreg = fmaf(fs[tid], nreg, a);
            float dp = qs[tid] * nreg;
#pragma unroll
            for (int o = 16; o; o >>= 1) dp += __shfl_xor_sync(0xffffffffu, dp, o);
            if ((tid & 31) == 0) denp[tid >> 5] = dp;
        }
        __syncthreads();

        if (tid < 64) {
            float num = red[0][tid] + red[1][tid] + red[2][tid] + red[3][tid];
            float den = fmaxf(denp[0] + denp[1], 1.0f);
            float ov  = (num / den) * ogs[tid] * (1.0f / (1.0f + expf(-xgs[tid])));
            __half h2 = __float2half_rn(ov);
            __half l2 = __float2half_rn(ov - __half2float(h2));
            hh[base1 + (size_t)t * 1024 + tid] = h2;
            hl[base1 + (size_t)t * 1024 + tid] = l2;
        }
    }
}

// ---------------------------------------------------------------------------
// Launch
// ---------------------------------------------------------------------------
extern "C" void kernel_launch(void* const* d_in, const int* in_sizes, int n_in,
                              void* d_out, int out_size)
{
    const float* x     = (const float*)d_in[0];
    const float* w_in  = (const float*)d_in[1];
    const float* w_q   = (const float*)d_in[2];
    const float* w_k   = (const float*)d_in[3];
    const float* w_v   = (const float*)d_in[4];
    const float* w_i   = (const float*)d_in[5];
    const float* b_i   = (const float*)d_in[6];
    const float* w_f   = (const float*)d_in[7];
    const float* b_f   = (const float*)d_in[8];
    const float* w_o   = (const float*)d_in[9];
    const float* b_o   = (const float*)d_in[10];
    const float* w_qn  = (const float*)d_in[11];
    const float* w_kn  = (const float*)d_in[12];
    const float* w_out = (const float*)d_in[13];
    float* out = (float*)d_out;

    float *xp, *pj, *dC, *dN, *G, *Cst, *Nst;
    __half *xh, *xl, *xph, *xpl, *hh, *hl, *wif, *w6f, *wof;
    cudaGetSymbolAddress((void**)&xp,  g_xp);
    cudaGetSymbolAddress((void**)&pj,  g_pj);
    cudaGetSymbolAddress((void**)&dC,  g_dC);
    cudaGetSymbolAddress((void**)&dN,  g_dN);
    cudaGetSymbolAddress((void**)&G,   g_G);
    cudaGetSymbolAddress((void**)&Cst, g_Cst);
    cudaGetSymbolAddress((void**)&Nst, g_Nst);
    cudaGetSymbolAddress((void**)&xh,  g_xh);
    cudaGetSymbolAddress((void**)&xl,  g_xl);
    cudaGetSymbolAddress((void**)&xph, g_xph);
    cudaGetSymbolAddress((void**)&xpl, g_xpl);
    cudaGetSymbolAddress((void**)&hh,  g_hh);
    cudaGetSymbolAddress((void**)&hl,  g_hl);
    cudaGetSymbolAddress((void**)&wif, g_wif);
    cudaGetSymbolAddress((void**)&w6f, g_w6f);
    cudaGetSymbolAddress((void**)&wof, g_wof);

    cudaFuncSetAttribute(gemm_f16<0>, cudaFuncAttributeMaxDynamicSharedMemorySize, GEMM_SMEM);
    cudaFuncSetAttribute(gemm_f16<1>, cudaFuncAttributeMaxDynamicSharedMemorySize, GEMM_SMEM);
    cudaFuncSetAttribute(gemm_f16<2>, cudaFuncAttributeMaxDynamicSharedMemorySize, GEMM_SMEM);

    // ---- pass 0: operand conversion ----
    split_h<<<(MROWS * 1024 / 4 + 255) / 256, 256>>>((const float4*)x, (uint2*)xh, (uint2*)xl, MROWS * 1024 / 4);
    cvt_h<<<(2048 * 1024 / 4 + 255) / 256, 256>>>((const float4*)w_in, (uint2*)wif, 2048 * 1024 / 4);
    cvt_h6<<<dim3(1024, 6), 256>>>((const float4*)w_q, (const float4*)w_k, (const float4*)w_v,
                                   (const float4*)w_i, (const float4*)w_f, (const float4*)w_o,
                                   (uint2*)w6f);
    cvt_h<<<(1024 * 1024 / 4 + 255) / 256, 256>>>((const float4*)w_out, (uint2*)wof, 1024 * 1024 / 4);

    dim3 blk(128);

    // ---- in_proj: [8192,2048] = x @ w_in^T, + fp16 split of output ----
    gemm_f16<0><<<dim3(2048 / 128, MROWS / 128), blk, GEMM_SMEM>>>(
        xh, xl, 1024, wif, nullptr, nullptr, nullptr, nullptr, nullptr,
        xp, 2048, xph, xpl);

    // ---- fused 6-projection GEMM: [8192,6144] ----
    gemm_f16<1><<<dim3(NPJ / 128, MROWS / 128), blk, GEMM_SMEM>>>(
        xph, xpl, 2048, w6f, w_qn, w_kn, b_i, b_f, b_o,
        pj, NPJ, nullptr, nullptr);

    // ---- chunk-parallel scan ----
    chunk_fwd  <<<NCID, 128>>>(pj, dC, dN, G);
    chunk_carry<<<BB * NH, 128>>>(dC, dN, G, Cst, Nst);
    chunk_out  <<<NCID, 128>>>(pj, xp, Cst, Nst, hh, hl);

    // ---- output projection ----
    gemm_f16<2><<<dim3(1024 / 128, MROWS / 128), blk, GEMM_SMEM>>>(
        hh, hl, 1024, wof, nullptr, nullptr, nullptr, nullptr, nullptr,
        out, 1024, nullptr, nullptr);
}

// round 11
// speedup vs baseline: 1.0513x; 1.0513x over previous
#include <cuda_runtime.h>
#include <cuda_fp16.h>
#include <math.h>
#include <stdint.h>

// Problem constants
#define BB   2
#define LL   4096
#define DIMD 1024
#define NH   16
#define HD   64
#define MROWS (BB * LL)          // 8192
#define KDIM 1024
#define CHUNK  64
#define NCHUNK (LL / CHUNK)      // 64
#define NCID   (BB * NH * NCHUNK) // 2048
#define NPJ  6144                // fused projection width

// ---------------------------------------------------------------------------
// Scratch
// ---------------------------------------------------------------------------
__device__ float g_xg[(size_t)MROWS * 1024];  // gate half of in_proj, fp32
__device__ float g_pj[(size_t)MROWS * NPJ];   // q|k|v|i|f|o fused, ld=6144
// fp16 operand buffers
__device__ __half g_xh  [(size_t)MROWS * 1024];
__device__ __half g_xl  [(size_t)MROWS * 1024];
__device__ __half g_hh  [(size_t)MROWS * 1024];
__device__ __half g_wgat[(size_t)1024 * 1024];   // w_in rows 1024..2047, fp16
__device__ __half g_wiT [(size_t)1024 * 1024];   // transpose of w_in rows 0..1023
__device__ __half g_w6h [(size_t)6 * 1024 * 1024];
__device__ __half g_w6l [(size_t)6 * 1024 * 1024];
__device__ __half g_wff [(size_t)NPJ * 1024];    // fused projection weight, fp16
__device__ __half g_wof [(size_t)1024 * 1024];
// chunked-scan scratch
__device__ float g_dC [(size_t)NCID * 4096];
__device__ float g_dN [(size_t)NCID * 64];
__device__ float g_G  [(size_t)NCID * 64];
__device__ float g_Cst[(size_t)NCID * 4096];
__device__ float g_Nst[(size_t)NCID * 64];

// ---------------------------------------------------------------------------
// helpers
// ---------------------------------------------------------------------------
__device__ __forceinline__ uint32_t packh(float x, float y) {
    __half hx = __float2half_rn(x);
    __half hy = __float2half_rn(y);
    return (uint32_t)__half_as_ushort(hx) | ((uint32_t)__half_as_ushort(hy) << 16);
}
__device__ __forceinline__ uint32_t packhl(float x, float y) {
    __half hx = __float2half_rn(x);
    __half hy = __float2half_rn(y);
    return packh(x - __half2float(hx), y - __half2float(hy));
}
__device__ __forceinline__ void cp16(uint32_t s, const void* g)
{
    asm volatile("cp.async.ca.shared.global [%0], [%1], 16;\n" :: "r"(s), "l"(g));
}

#define LDSM_X4(r0, r1, r2, r3, addr) \
    asm volatile("ldmatrix.sync.aligned.m8n8.x4.shared.b16 {%0,%1,%2,%3}, [%4];" \
                 : "=r"(r0), "=r"(r1), "=r"(r2), "=r"(r3) : "r"(addr))

#define MMA_F16(d, a, b0, b1) \
    asm volatile("mma.sync.aligned.m16n8k16.row.col.f32.f16.f16.f32 " \
                 "{%0,%1,%2,%3}, {%4,%5,%6,%7}, {%8,%9}, {%0,%1,%2,%3};" \
                 : "+f"((d)[0]), "+f"((d)[1]), "+f"((d)[2]), "+f"((d)[3]) \
                 : "r"((a)[0]), "r"((a)[1]), "r"((a)[2]), "r"((a)[3]), \
                   "r"(b0), "r"(b1))

// ---------------------------------------------------------------------------
// Pass 0 kernels
// ---------------------------------------------------------------------------
// fp32 -> (hi, lo) fp16 split
__global__ void split_h(const float4* __restrict__ s, uint2* __restrict__ hi,
                        uint2* __restrict__ lo, int n4)
{
    int i = blockIdx.x * 256 + threadIdx.x;
    if (i >= n4) return;
    float4 v = s[i];
    uint2 h, l;
    h.x = packh(v.x, v.y);  h.y = packh(v.z, v.w);
    l.x = packhl(v.x, v.y); l.y = packhl(v.z, v.w);
    hi[i] = h; lo[i] = l;
}

// fp32 -> fp16 single
__global__ void cvt_h(const float4* __restrict__ s, uint2* __restrict__ d, int n4)
{
    int i = blockIdx.x * 256 + threadIdx.x;
    if (i >= n4) return;
    float4 v = s[i];
    uint2 o;
    o.x = packh(v.x, v.y); o.y = packh(v.z, v.w);
    d[i] = o;
}

// 6 projection weights -> hi/lo fp16, one launch. grid (1024, 6).
__global__ void split_h6(const float4* __restrict__ s0, const float4* __restrict__ s1,
                         const float4* __restrict__ s2, const float4* __restrict__ s3,
                         const float4* __restrict__ s4, const float4* __restrict__ s5,
                         uint2* __restrict__ hi, uint2* __restrict__ lo)
{
    const int n4 = 1024 * 1024 / 4;
    int i = blockIdx.x * 256 + threadIdx.x;
    if (i >= n4) return;
    const float4* s;
    switch (blockIdx.y) {
        case 0: s = s0; break; case 1: s = s1; break; case 2: s = s2; break;
        case 3: s = s3; break; case 4: s = s4; break; default: s = s5; break;
    }
    float4 v = s[i];
    uint2 h, l;
    h.x = packh(v.x, v.y);  h.y = packh(v.z, v.w);
    l.x = packhl(v.x, v.y); l.y = packhl(v.z, v.w);
    size_t o = (size_t)blockIdx.y * n4 + i;
    hi[o] = h; lo[o] = l;
}

// transpose w_in[0:1024,:] (fp32 [1024,1024]) -> wiT fp16 [1024,1024]
__global__ void transpose_wi(const float* __restrict__ w, __half* __restrict__ wt)
{
    __shared__ float tile[32][33];
    const int bx = blockIdx.x * 32, by = blockIdx.y * 32;
    const int tx = threadIdx.x & 31, ty = threadIdx.x >> 5;   // 32x8
#pragma unroll
    for (int dy = 0; dy < 32; dy += 8)
        tile[ty + dy][tx] = w[(size_t)(by + ty + dy) * 1024 + bx + tx];
    __syncthreads();
#pragma unroll
    for (int dy = 0; dy < 32; dy += 8)
        wt[(size_t)(bx + ty + dy) * 1024 + by + tx] = __float2half_rn(tile[tx][ty + dy]);
}

// ---------------------------------------------------------------------------
// cp.async pipelined fp16 GEMM.  C[M,N] = (Ah[+Al])[M,K] @ B[N,K]^T, K=1024,
// CTA 128x128, warp 64x64, BK=32, 4 stages, 2 CTAs/SM.
// TERMS: 2 = split A (hi+lo, 2 MMAs); 1 = single fp16 A (1 MMA).
// MODE:  0 = fp16-only output (Chh; for Wfused)
//        1 = fused projections, N=6144, per-1024-col-segment epilogue
//        2 = plain fp32 C
// ---------------------------------------------------------------------------
#define STAGES 4
#define SECB   8192
#define STAGEB (3 * SECB)             // 24576
#define GEMM_SMEM (STAGES * STAGEB)   // 98304

template <int MODE, int TERMS>
__global__ void __launch_bounds__(128, 2)
gemm_f16(const __half* __restrict__ Ah, const __half* __restrict__ Al, int lda,
         const __half* __restrict__ B,
         const float* __restrict__ q0, const float* __restrict__ q1,
         const float* __restrict__ q2, const float* __restrict__ q3,
         const float* __restrict__ q4,
         float* __restrict__ C, int ldc,
         __half* __restrict__ Chh)
{
    extern __shared__ __align__(128) char smem[];
    const uint32_t sbase = (uint32_t)__cvta_generic_to_shared(smem);

    const int tid  = threadIdx.x;
    const int w    = tid >> 5;
    const int lane = tid & 31;
    const int wm   = w & 1;          // M half (64 rows)
    const int wn   = w >> 1;         // N half (64 cols)

    const int m0 = blockIdx.y * 128;
    const int n0 = blockIdx.x * 128;

    const __half* Ahp = Ah + (size_t)m0 * lda;
    const __half* Alp = (TERMS == 2) ? (Al + (size_t)m0 * lda) : nullptr;
    const __half* Bp  = B  + (size_t)n0 * KDIM;

    // loader: TERMS==2 -> 1536 chunks (Ah|Al|B), 12/thread; TERMS==1 -> 1024 (Ah|B), 8/thread
    auto load_stage = [&](int buf, int k0) {
        const uint32_t db = sbase + (uint32_t)(buf * STAGEB);
        const int NCH = (TERMS == 2) ? 12 : 8;
#pragma unroll
        for (int i = 0; i < NCH; i++) {
            const int ci  = tid + i * 128;
            const int s2  = ci >> 9;
            const int r   = (ci >> 2) & 127;
            const int kq  = ci & 3;
            const __half* gp;
            uint32_t secoff;
            if (TERMS == 2) {
                if      (s2 == 0) { gp = Ahp + (size_t)r * lda; secoff = 0; }
                else if (s2 == 1) { gp = Alp + (size_t)r * lda; secoff = SECB; }
                else              { gp = Bp  + (size_t)r * KDIM; secoff = 2 * SECB; }
            } else {
                if (s2 == 0) { gp = Ahp + (size_t)r * lda; secoff = 0; }
                else         { gp = Bp  + (size_t)r * KDIM; secoff = 2 * SECB; }
            }
            gp += k0 + kq * 8;
            const uint32_t d = db + secoff + (uint32_t)(r * 64 + ((kq * 16) ^ ((r * 8) & 0x30)));
            cp16(d, gp);
        }
    };

    // ldmatrix per-lane addressing (SW64)
    const int a_r  = (lane & 7) + ((lane >> 3) & 1) * 8;
    const int ak2  = ((lane >> 4) & 1) * 16;
    const uint32_t axr = (uint32_t)((a_r << 3) & 0x30);
    const int g    = lane >> 3;
    const int b_r  = ((g >> 1) * 8) + (lane & 7);
    const int bk2  = (g & 1) * 16;
    const uint32_t bxr = (uint32_t)((b_r << 3) & 0x30);

    uint32_t aoff[4], boff[4];
#pragma unroll
    for (int mi = 0; mi < 4; mi++) aoff[mi] = (uint32_t)((wm * 64 + mi * 16 + a_r) * 64);
#pragma unroll
    for (int gi = 0; gi < 4; gi++) boff[gi] = (uint32_t)(2 * SECB + (wn * 64 + gi * 16 + b_r) * 64);

    float acc[4][8][4] = {};

    load_stage(0, 0);
    asm volatile("cp.async.commit_group;\n");
    load_stage(1, 32);
    asm volatile("cp.async.commit_group;\n");
    load_stage(2, 64);
    asm volatile("cp.async.commit_group;\n");

    const int S = KDIM / 32;   // 32
    for (int s = 0; s < S; s++) {
        asm volatile("cp.async.wait_group 2;\n" ::: "memory");
        __syncthreads();
        if (s + 3 < S) load_stage((s + 3) & (STAGES - 1), (s + 3) * 32);
        asm volatile("cp.async.commit_group;\n");

        const uint32_t bb = sbase + (uint32_t)((s & (STAGES - 1)) * STAGEB);
#pragma unroll
        for (int kb = 0; kb < 2; kb++) {
            const uint32_t kx = (uint32_t)(kb * 32);
            uint32_t Bf[4][4];
#pragma unroll
            for (int gi = 0; gi < 4; gi++) {
                const uint32_t ba = bb + boff[gi] + ((kx + bk2) ^ bxr);
                LDSM_X4(Bf[gi][0], Bf[gi][1], Bf[gi][2], Bf[gi][3], ba);
            }
            // hi term
            {
                uint32_t Af[4][4];
#pragma unroll
                for (int mi = 0; mi < 4; mi++) {
                    const uint32_t aa = bb + aoff[mi] + ((kx + ak2) ^ axr);
                    LDSM_X4(Af[mi][0], Af[mi][1], Af[mi][2], Af[mi][3], aa);
                }
#pragma unroll
                for (int gi = 0; gi < 4; gi++)
#pragma unroll
                    for (int mi = 0; mi < 4; mi++)
#pragma unroll
                        for (int hf = 0; hf < 2; hf++)
                            MMA_F16(acc[mi][gi * 2 + hf], Af[mi], Bf[gi][2 * hf], Bf[gi][2 * hf + 1]);
            }
            // lo term
            if (TERMS == 2) {
                uint32_t Af[4][4];
#pragma unroll
                for (int mi = 0; mi < 4; mi++) {
                    const uint32_t aa = bb + aoff[mi] + ((kx + ak2) ^ axr) + SECB;
                    LDSM_X4(Af[mi][0], Af[mi][1], Af[mi][2], Af[mi][3], aa);
                }
#pragma unroll
                for (int gi = 0; gi < 4; gi++)
#pragma unroll
                    for (int mi = 0; mi < 4; mi++)
#pragma unroll
                        for (int hf = 0; hf < 2; hf++)
                            MMA_F16(acc[mi][gi * 2 + hf], Af[mi], Bf[gi][2 * hf], Bf[gi][2 * hf + 1]);
            }
        }
    }

    const int qr = lane >> 2;
    const int qc = (lane & 3) * 2;
    const int seg = blockIdx.x >> 3;   // MODE 1: 1024-col segment

    if (MODE == 1 && seg < 2) {
        const float* wn_ = (seg == 0) ? q0 : q1;
#pragma unroll
        for (int mi = 0; mi < 4; mi++)
#pragma unroll
            for (int rh = 0; rh < 2; rh++) {
                float ss = 0.0f;
#pragma unroll
                for (int ti = 0; ti < 8; ti++) {
                    float a = acc[mi][ti][2 * rh], b2 = acc[mi][ti][2 * rh + 1];
                    ss += a * a + b2 * b2;
                }
                ss += __shfl_xor_sync(0xffffffffu, ss, 1);
                ss += __shfl_xor_sync(0xffffffffu, ss, 2);
                const float sc = rsqrtf(ss * (1.0f / 64.0f) + 1e-6f);
#pragma unroll
                for (int ti = 0; ti < 8; ti++) {
                    acc[mi][ti][2 * rh]     *= sc * wn_[ti * 8 + qc];
                    acc[mi][ti][2 * rh + 1] *= sc * wn_[ti * 8 + qc + 1];
                }
            }
    }

#pragma unroll
    for (int mi = 0; mi < 4; mi++) {
#pragma unroll
        for (int ti = 0; ti < 8; ti++) {
            const int col = n0 + wn * 64 + ti * 8 + qc;
            float b0 = 0.f, b1 = 0.f;
            if (MODE == 1 && seg >= 3) {
                const float* bp = (seg == 3) ? q2 : (seg == 4) ? q3 : q4;
                const int cs = col & 1023;
                b0 = bp[cs]; b1 = bp[cs + 1];
            }
#pragma unroll
            for (int rh = 0; rh < 2; rh++) {
                const int row = m0 + wm * 64 + mi * 16 + rh * 8 + qr;
                float x0 = acc[mi][ti][2 * rh + 0];
                float x1 = acc[mi][ti][2 * rh + 1];
                if (MODE == 1) {
                    if (seg == 3)      { x0 = expf(x0 + b0); x1 = expf(x1 + b1); }
                    else if (seg >= 4) { x0 = 1.0f / (1.0f + expf(-(x0 + b0)));
                                         x1 = 1.0f / (1.0f + expf(-(x1 + b1))); }
                }
                if (MODE == 0) {
                    *(uint32_t*)&Chh[(size_t)row * ldc + col] = packh(x0, x1);
                } else {
                    *(float2*)&C[(size_t)row * ldc + col] = make_float2(x0, x1);
                }
            }
        }
    }
}

// ---------------------------------------------------------------------------
// Chunk-parallel mLSTM scan
// ---------------------------------------------------------------------------
__global__ void __launch_bounds__(128, 4)
chunk_fwd(const float* __restrict__ pj,
          float* __restrict__ dC, float* __restrict__ dN, float* __restrict__ G)
{
    __shared__ float stage[2][4][64];

    const int tid = threadIdx.x;
    const int cid = blockIdx.x;
    const int j   = cid & (NCHUNK - 1);
    const int bh  = cid >> 6;
    const int b   = bh >> 4;
    const int h   = bh & 15;
    const size_t base6 = ((size_t)b * LL + (size_t)j * CHUNK) * NPJ + (size_t)h * 64;

    const float* srcs[4] = { pj + base6 + 1024, pj + base6 + 2048,
                             pj + base6 + 3072, pj + base6 + 4096 };
    const int  arr = tid >> 4;
    const int  ch  = tid & 15;
    const bool loader = (tid < 64);
    const float* mySrc = srcs[loader ? arr : 0] + ch * 4;
    const uint32_t mydst0 = (uint32_t)__cvta_generic_to_shared(&stage[0][0][0]) + (arr * 64 + ch * 4) * 4;
    const uint32_t mydst1 = mydst0 + 4 * 64 * 4;

    if (loader) cp16(mydst0, mySrc);
    asm volatile("cp.async.commit_group;\n");

    const int r = tid >> 5;
    const int c = tid & 31;
    float C0[16], C1[16];
#pragma unroll
    for (int i = 0; i < 16; i++) { C0[i] = 0.0f; C1[i] = 0.0f; }
    float nreg = 0.0f, greg = 1.0f;

    for (int t = 0; t < CHUNK; t++) {
        asm volatile("cp.async.wait_group 0;\n" ::: "memory");
        __syncthreads();
        const int cur = t & 1;

        if (t + 1 < CHUNK && loader)
            cp16(cur ? mydst0 : mydst1, mySrc + (size_t)(t + 1) * NPJ);
        asm volatile("cp.async.commit_group;\n");

        const float* S   = &stage[cur][0][0];
        const float* ks  = S;
        const float* vs  = S + 64;
        const float* is_ = S + 128;
        const float* fs  = S + 192;

        float v0 = vs[c], v1 = vs[c + 32];

#pragma unroll
        for (int dd = 0; dd < 16; dd += 4) {
            int d = r * 16 + dd;
            float4 f4 = *(const float4*)&fs[d];
            float4 i4 = *(const float4*)&is_[d];
            float4 k4 = *(const float4*)&ks[d];
            float a0 = i4.x * k4.x, a1 = i4.y * k4.y, a2 = i4.z * k4.z, a3 = i4.w * k4.w;
            C0[dd+0] = fmaf(f4.x, C0[dd+0], a0 * v0); C1[dd+0] = fmaf(f4.x, C1[dd+0], a0 * v1);
            C0[dd+1] = fmaf(f4.y, C0[dd+1], a1 * v0); C1[dd+1] = fmaf(f4.y, C1[dd+1], a1 * v1);
            C0[dd+2] = fmaf(f4.z, C0[dd+2], a2 * v0); C1[dd+2] = fmaf(f4.z, C1[dd+2], a2 * v1);
            C0[dd+3] = fmaf(f4.w, C0[dd+3], a3 * v0); C1[dd+3] = fmaf(f4.w, C1[dd+3], a3 * v1);
        }

        if (tid < 64) {
            float ft = fs[tid];
            nreg = fmaf(ft, nreg, is_[tid] * ks[tid]);
            greg *= ft;
        }
        __syncthreads();
    }

    float* dCp = dC + (size_t)cid * 4096;
#pragma unroll
    for (int dd = 0; dd < 16; dd++) {
        dCp[(r * 16 + dd) * 64 + c]      = C0[dd];
        dCp[(r * 16 + dd) * 64 + c + 32] = C1[dd];
    }
    if (tid < 64) {
        dN[(size_t)cid * 64 + tid] = nreg;
        G [(size_t)cid * 64 + tid] = greg;
    }
}

__global__ void __launch_bounds__(128, 1)
chunk_carry(const float* __restrict__ dC, const float* __restrict__ dN,
            const float* __restrict__ G,
            float* __restrict__ Cst, float* __restrict__ Nst)
{
    __shared__ float gs[64], dns[64];
    const int tid = threadIdx.x;
    const int bh  = blockIdx.x;
    const int r = tid >> 5;
    const int c = tid & 31;

    float C0[16], C1[16];
#pragma unroll
    for (int i = 0; i < 16; i++) { C0[i] = 0.0f; C1[i] = 0.0f; }
    float n = 0.0f;

    for (int j = 0; j < NCHUNK; j++) {
        const size_t cid = (size_t)bh * NCHUNK + j;
        float* Cp = Cst + cid * 4096;
        const float* Dp = dC + cid * 4096;

        if (tid < 64) {
            Nst[cid * 64 + tid] = n;
            gs[tid]  = G [cid * 64 + tid];
            dns[tid] = dN[cid * 64 + tid];
        }
#pragma unroll
        for (int dd = 0; dd < 16; dd++) {
            Cp[(r * 16 + dd) * 64 + c]      = C0[dd];
            Cp[(r * 16 + dd) * 64 + c + 32] = C1[dd];
        }
        __syncthreads();
#pragma unroll
        for (int dd = 0; dd < 16; dd++) {
            float gd = gs[r * 16 + dd];
            C0[dd] = fmaf(gd, C0[dd], Dp[(r * 16 + dd) * 64 + c]);
            C1[dd] = fmaf(gd, C1[dd], Dp[(r * 16 + dd) * 64 + c + 32]);
        }
        if (tid < 64) n = fmaf(gs[tid], n, dns[tid]);
        __syncthreads();
    }
}

__global__ void __launch_bounds__(128, 4)
chunk_out(const float* __restrict__ pj, const float* __restrict__ xg,
          const float* __restrict__ Cst, const float* __restrict__ Nst,
          __half* __restrict__ hh)
{
    __shared__ float stage[2][7][64];
    __shared__ float red[4][64];
    __shared__ float denp[2];

    const int tid = threadIdx.x;
    const int cid = blockIdx.x;
    const int j   = cid & (NCHUNK - 1);
    const int bh  = cid >> 6;
    const int b   = bh >> 4;
    const int h   = bh & 15;
    const size_t base6 = ((size_t)b * LL + (size_t)j * CHUNK) * NPJ + (size_t)h * 64;
    const size_t base1 = ((size_t)b * LL + (size_t)j * CHUNK) * 1024 + (size_t)h * 64;

    const float* srcs[8] = { pj + base6,        pj + base6 + 1024, pj + base6 + 2048,
                             pj + base6 + 3072, pj + base6 + 4096, pj + base6 + 5120,
                             xg + base1,        pj + base6 };

    const int  arr = tid >> 4;
    const int  ch  = tid & 15;
    const bool loader = (tid < 112);
    const float* mySrc    = srcs[arr] + ch * 4;
    const size_t mystride = (arr == 6) ? 1024 : NPJ;
    const uint32_t mydst0 = (uint32_t)__cvta_generic_to_shared(&stage[0][0][0]) + (arr * 64 + ch * 4) * 4;
    const uint32_t mydst1 = mydst0 + 7 * 64 * 4;

    if (loader) cp16(mydst0, mySrc);
    asm volatile("cp.async.commit_group;\n");

    const int r = tid >> 5;
    const int c = tid & 31;

    const float* Cp = Cst + (size_t)cid * 4096;
    float C0[16], C1[16];
#pragma unroll
    for (int dd = 0; dd < 16; dd++) {
        C0[dd] = Cp[(r * 16 + dd) * 64 + c];
        C1[dd] = Cp[(r * 16 + dd) * 64 + c + 32];
    }
    float nreg = (tid < 64) ? Nst[(size_t)cid * 64 + tid] : 0.0f;

    for (int t = 0; t < CHUNK; t++) {
        asm volatile("cp.async.wait_group 0;\n" ::: "memory");
        __syncthreads();
        const int cur = t & 1;

        if (t + 1 < CHUNK && loader)
            cp16(cur ? mydst0 : mydst1, mySrc + (size_t)(t + 1) * mystride);
        asm volatile("cp.async.commit_group;\n");

        const float* S   = &stage[cur][0][0];
        const float* qs  = S;
        const float* ks  = S + 64;
        const float* vs  = S + 128;
        const float* is_ = S + 192;
        const float* fs  = S + 256;
        const float* ogs = S + 320;
        const float* xgs = S + 384;

        float v0 = vs[c], v1 = vs[c + 32];
        float pn0 = 0.0f, pn1 = 0.0f;

#define ROWOP(ff, qq, aa, idx) { float _a = (aa);                              \
        C0[idx] = fmaf((ff), C0[idx], _a * v0); pn0 = fmaf((qq), C0[idx], pn0);\
        C1[idx] = fmaf((ff), C1[idx], _a * v1); pn1 = fmaf((qq), C1[idx], pn1); }

#pragma unroll
        for (int dd = 0; dd < 16; dd += 4) {
            int d = r * 16 + dd;
            float4 f4 = *(const float4*)&fs[d];
            float4 q4 = *(const float4*)&qs[d];
            float4 i4 = *(const float4*)&is_[d];
            float4 k4 = *(const float4*)&ks[d];
            ROWOP(f4.x, q4.x, i4.x * k4.x, dd + 0);
            ROWOP(f4.y, q4.y, i4.y * k4.y, dd + 1);
            ROWOP(f4.z, q4.z, i4.z * k4.z, dd + 2);
            ROWOP(f4.w, q4.w, i4.w * k4.w, dd + 3);
        }
#undef ROWOP

        red[r][c]      = pn0;
        red[r][c + 32] = pn1;

        if (tid < 64) {
            float a = is_[tid] * ks[tid];
            nreg = fmaf(fs[tid], nreg, a);
            float dp = qs[tid] * nreg;
#pragma unroll
            for (int o = 16; o; o >>= 1) dp += __shfl_xor_sync(0xffffffffu, dp, o);
            if ((tid & 31) == 0) denp[tid >> 5] = dp;
        }
        __syncthreads();

        if (tid < 64) {
            float num = red[0][tid] + red[1][tid] + red[2][tid] + red[3][tid];
            float den = fmaxf(denp[0] + denp[1], 1.0f);
            float ov  = (num / den) * ogs[tid] * (1.0f / (1.0f + expf(-xgs[tid])));
            hh[base1 + (size_t)t * 1024 + tid] = __float2half_rn(ov);
        }
    }
}

// ---------------------------------------------------------------------------
// Launch
// ---------------------------------------------------------------------------
extern "C" void kernel_launch(void* const* d_in, const int* in_sizes, int n_in,
                              void* d_out, int out_size)
{
    const float* x     = (const float*)d_in[0];
    const float* w_in  = (const float*)d_in[1];
    const float* w_q   = (const float*)d_in[2];
    const float* w_k   = (const float*)d_in[3];
    const float* w_v   = (const float*)d_in[4];
    const float* w_i   = (const float*)d_in[5];
    const float* b_i   = (const float*)d_in[6];
    const float* w_f   = (const float*)d_in[7];
    const float* b_f   = (const float*)d_in[8];
    const float* w_o   = (const float*)d_in[9];
    const float* b_o   = (const float*)d_in[10];
    const float* w_qn  = (const float*)d_in[11];
    const float* w_kn  = (const float*)d_in[12];
    const float* w_out = (const float*)d_in[13];
    float* out = (float*)d_out;

    float *xg, *pj, *dC, *dN, *G, *Cst, *Nst;
    __half *xh, *xl, *hh, *wgat, *wiT, *w6h, *w6l, *wff, *wof;
    cudaGetSymbolAddress((void**)&xg,  g_xg);
    cudaGetSymbolAddress((void**)&pj,  g_pj);
    cudaGetSymbolAddress((void**)&dC,  g_dC);
    cudaGetSymbolAddress((void**)&dN,  g_dN);
    cudaGetSymbolAddress((void**)&G,   g_G);
    cudaGetSymbolAddress((void**)&Cst, g_Cst);
    cudaGetSymbolAddress((void**)&Nst, g_Nst);
    cudaGetSymbolAddress((void**)&xh,  g_xh);
    cudaGetSymbolAddress((void**)&xl,  g_xl);
    cudaGetSymbolAddress((void**)&hh,  g_hh);
    cudaGetSymbolAddress((void**)&wgat, g_wgat);
    cudaGetSymbolAddress((void**)&wiT,  g_wiT);
    cudaGetSymbolAddress((void**)&w6h,  g_w6h);
    cudaGetSymbolAddress((void**)&w6l,  g_w6l);
    cudaGetSymbolAddress((void**)&wff,  g_wff);
    cudaGetSymbolAddress((void**)&wof,  g_wof);

    cudaFuncSetAttribute(gemm_f16<0,2>, cudaFuncAttributeMaxDynamicSharedMemorySize, GEMM_SMEM);
    cudaFuncSetAttribute(gemm_f16<1,2>, cudaFuncAttributeMaxDynamicSharedMemorySize, GEMM_SMEM);
    cudaFuncSetAttribute(gemm_f16<2,2>, cudaFuncAttributeMaxDynamicSharedMemorySize, GEMM_SMEM);
    cudaFuncSetAttribute(gemm_f16<2,1>, cudaFuncAttributeMaxDynamicSharedMemorySize, GEMM_SMEM);

    // ---- pass 0: operand conversion ----
    const int NSQ4 = 1024 * 1024 / 4;
    split_h<<<(MROWS * 1024 / 4 + 255) / 256, 256>>>((const float4*)x, (uint2*)xh, (uint2*)xl, MROWS * 1024 / 4);
    transpose_wi<<<dim3(32, 32), 256>>>(w_in, wiT);                              // w_in rows 0..1023, transposed
    cvt_h<<<(NSQ4 + 255) / 256, 256>>>((const float4*)(w_in + (size_t)1024 * 1024), (uint2*)wgat, NSQ4);
    split_h6<<<dim3(1024, 6), 256>>>((const float4*)w_q, (const float4*)w_k, (const float4*)w_v,
                                     (const float4*)w_i, (const float4*)w_f, (const float4*)w_o,
                                     (uint2*)w6h, (uint2*)w6l);
    cvt_h<<<(NSQ4 + 255) / 256, 256>>>((const float4*)w_out, (uint2*)wof, NSQ4);

    dim3 blk(128);

    // ---- Wfused[6144,1024] = Wproj @ Wi_inner  (A = w6 hi/lo, B = WiT) ----
    gemm_f16<0,2><<<dim3(1024 / 128, NPJ / 128), blk, GEMM_SMEM>>>(
        w6h, w6l, 1024, wiT, nullptr, nullptr, nullptr, nullptr, nullptr,
        nullptr, 1024, wff);

    // ---- in_proj gate half: xg[8192,1024] = x @ w_in[1024:2048]^T ----
    gemm_f16<2,2><<<dim3(1024 / 128, MROWS / 128), blk, GEMM_SMEM>>>(
        xh, xl, 1024, wgat, nullptr, nullptr, nullptr, nullptr, nullptr,
        xg, 1024, nullptr);

    // ---- fused projections directly from x: pj[8192,6144] = x @ Wfused^T ----
    gemm_f16<1,2><<<dim3(NPJ / 128, MROWS / 128), blk, GEMM_SMEM>>>(
        xh, xl, 1024, wff, w_qn, w_kn, b_i, b_f, b_o,
        pj, NPJ, nullptr);

    // ---- chunk-parallel scan ----
    chunk_fwd  <<<NCID, 128>>>(pj, dC, dN, G);
    chunk_carry<<<BB * NH, 128>>>(dC, dN, G, Cst, Nst);
    chunk_out  <<<NCID, 128>>>(pj, xg, Cst, Nst, hh);

    // ---- output projection (single-term fp16 A) ----
    gemm_f16<2,1><<<dim3(1024 / 128, MROWS / 128), blk, GEMM_SMEM>>>(
        hh, nullptr, 1024, wof, nullptr, nullptr, nullptr, nullptr, nullptr,
        out, 1024, nullptr);
}

// round 12
// speedup vs baseline: 1.4053x; 1.3368x over previous
#include <cuda_runtime.h>
#include <cuda_fp16.h>
#include <math.h>
#include <stdint.h>

// Problem constants
#define BB   2
#define LL   4096
#define DIMD 1024
#define NH   16
#define HD   64
#define MROWS (BB * LL)          // 8192
#define KDIM 1024
#define CHUNK  64
#define NCHUNK (LL / CHUNK)      // 64
#define NCID   (BB * NH * NCHUNK) // 2048
#define NPJ  7168                // fused projection width: q|k|v|i|f|o|gate

// ---------------------------------------------------------------------------
// Scratch
// ---------------------------------------------------------------------------
__device__ float g_pj[(size_t)MROWS * NPJ];   // q|k|v|i|f|o|xgate, ld=7168
// fp16 operand buffers
__device__ __half g_xh  [(size_t)MROWS * 1024];
__device__ __half g_hh  [(size_t)MROWS * 1024];
__device__ __half g_wiT [(size_t)1024 * 1024];   // transpose of w_in rows 0..1023
__device__ __half g_w6h [(size_t)6 * 1024 * 1024];
__device__ __half g_w6l [(size_t)6 * 1024 * 1024];
__device__ __half g_wff [(size_t)NPJ * 1024];    // fused weight: [Wproj@Wi | w_gate]
__device__ __half g_wof [(size_t)1024 * 1024];
// chunked-scan scratch
__device__ float g_dC [(size_t)NCID * 4096];
__device__ float g_dN [(size_t)NCID * 64];
__device__ float g_G  [(size_t)NCID * 64];
__device__ float g_Cst[(size_t)NCID * 4096];
__device__ float g_Nst[(size_t)NCID * 64];

// ---------------------------------------------------------------------------
// helpers
// ---------------------------------------------------------------------------
__device__ __forceinline__ uint32_t packh(float x, float y) {
    __half hx = __float2half_rn(x);
    __half hy = __float2half_rn(y);
    return (uint32_t)__half_as_ushort(hx) | ((uint32_t)__half_as_ushort(hy) << 16);
}
__device__ __forceinline__ uint32_t packhl(float x, float y) {
    __half hx = __float2half_rn(x);
    __half hy = __float2half_rn(y);
    return packh(x - __half2float(hx), y - __half2float(hy));
}
__device__ __forceinline__ void cp16(uint32_t s, const void* g)
{
    asm volatile("cp.async.ca.shared.global [%0], [%1], 16;\n" :: "r"(s), "l"(g));
}

#define LDSM_X4(r0, r1, r2, r3, addr) \
    asm volatile("ldmatrix.sync.aligned.m8n8.x4.shared.b16 {%0,%1,%2,%3}, [%4];" \
                 : "=r"(r0), "=r"(r1), "=r"(r2), "=r"(r3) : "r"(addr))

#define MMA_F16(d, a, b0, b1) \
    asm volatile("mma.sync.aligned.m16n8k16.row.col.f32.f16.f16.f32 " \
                 "{%0,%1,%2,%3}, {%4,%5,%6,%7}, {%8,%9}, {%0,%1,%2,%3};" \
                 : "+f"((d)[0]), "+f"((d)[1]), "+f"((d)[2]), "+f"((d)[3]) \
                 : "r"((a)[0]), "r"((a)[1]), "r"((a)[2]), "r"((a)[3]), \
                   "r"(b0), "r"(b1))

// ---------------------------------------------------------------------------
// Pass 0 kernels
// ---------------------------------------------------------------------------
// fp32 -> fp16 single
__global__ void cvt_h(const float4* __restrict__ s, uint2* __restrict__ d, int n4)
{
    int i = blockIdx.x * 256 + threadIdx.x;
    if (i >= n4) return;
    float4 v = s[i];
    uint2 o;
    o.x = packh(v.x, v.y); o.y = packh(v.z, v.w);
    d[i] = o;
}

// 6 projection weights -> hi/lo fp16, one launch. grid (1024, 6).
__global__ void split_h6(const float4* __restrict__ s0, const float4* __restrict__ s1,
                         const float4* __restrict__ s2, const float4* __restrict__ s3,
                         const float4* __restrict__ s4, const float4* __restrict__ s5,
                         uint2* __restrict__ hi, uint2* __restrict__ lo)
{
    const int n4 = 1024 * 1024 / 4;
    int i = blockIdx.x * 256 + threadIdx.x;
    if (i >= n4) return;
    const float4* s;
    switch (blockIdx.y) {
        case 0: s = s0; break; case 1: s = s1; break; case 2: s = s2; break;
        case 3: s = s3; break; case 4: s = s4; break; default: s = s5; break;
    }
    float4 v = s[i];
    uint2 h, l;
    h.x = packh(v.x, v.y);  h.y = packh(v.z, v.w);
    l.x = packhl(v.x, v.y); l.y = packhl(v.z, v.w);
    size_t o = (size_t)blockIdx.y * n4 + i;
    hi[o] = h; lo[o] = l;
}

// transpose w_in[0:1024,:] (fp32 [1024,1024]) -> wiT fp16 [1024,1024]
__global__ void transpose_wi(const float* __restrict__ w, __half* __restrict__ wt)
{
    __shared__ float tile[32][33];
    const int bx = blockIdx.x * 32, by = blockIdx.y * 32;
    const int tx = threadIdx.x & 31, ty = threadIdx.x >> 5;   // 32x8
#pragma unroll
    for (int dy = 0; dy < 32; dy += 8)
        tile[ty + dy][tx] = w[(size_t)(by + ty + dy) * 1024 + bx + tx];
    __syncthreads();
#pragma unroll
    for (int dy = 0; dy < 32; dy += 8)
        wt[(size_t)(bx + ty + dy) * 1024 + by + tx] = __float2half_rn(tile[tx][ty + dy]);
}

// ---------------------------------------------------------------------------
// cp.async pipelined fp16 GEMM.  C[M,N] = (Ah[+Al])[M,K] @ B[N,K]^T, K=1024,
// CTA 128x128, warp 64x64, BK=32, 4 stages, 2 CTAs/SM.
// TERMS: 2 = split A (hi+lo, 2 MMAs); 1 = single fp16 A (1 MMA).
// MODE:  0 = fp16-only output (Chh; for Wfused)
//        1 = fused projections, N=7168, per-1024-col-segment epilogue:
//            seg0/1 rmsnorm, seg2 plain, seg3 exp+bias, seg4/5 sigmoid+bias,
//            seg6 plain (raw gate)
//        2 = plain fp32 C
// ---------------------------------------------------------------------------
#define STAGES 4
#define SECB   8192
#define STAGEB (3 * SECB)             // 24576
#define GEMM_SMEM (STAGES * STAGEB)   // 98304

template <int MODE, int TERMS>
__global__ void __launch_bounds__(128, 2)
gemm_f16(const __half* __restrict__ Ah, const __half* __restrict__ Al, int lda,
         const __half* __restrict__ B,
         const float* __restrict__ q0, const float* __restrict__ q1,
         const float* __restrict__ q2, const float* __restrict__ q3,
         const float* __restrict__ q4,
         float* __restrict__ C, int ldc,
         __half* __restrict__ Chh)
{
    extern __shared__ __align__(128) char smem[];
    const uint32_t sbase = (uint32_t)__cvta_generic_to_shared(smem);

    const int tid  = threadIdx.x;
    const int w    = tid >> 5;
    const int lane = tid & 31;
    const int wm   = w & 1;          // M half (64 rows)
    const int wn   = w >> 1;         // N half (64 cols)

    const int m0 = blockIdx.y * 128;
    const int n0 = blockIdx.x * 128;

    const __half* Ahp = Ah + (size_t)m0 * lda;
    const __half* Alp = (TERMS == 2) ? (Al + (size_t)m0 * lda) : nullptr;
    const __half* Bp  = B  + (size_t)n0 * KDIM;

    // loader: TERMS==2 -> 1536 chunks (Ah|Al|B), 12/thread; TERMS==1 -> 1024 (Ah|B), 8/thread
    auto load_stage = [&](int buf, int k0) {
        const uint32_t db = sbase + (uint32_t)(buf * STAGEB);
        const int NCH = (TERMS == 2) ? 12 : 8;
#pragma unroll
        for (int i = 0; i < NCH; i++) {
            const int ci  = tid + i * 128;
            const int s2  = ci >> 9;
            const int r   = (ci >> 2) & 127;
            const int kq  = ci & 3;
            const __half* gp;
            uint32_t secoff;
            if (TERMS == 2) {
                if      (s2 == 0) { gp = Ahp + (size_t)r * lda; secoff = 0; }
                else if (s2 == 1) { gp = Alp + (size_t)r * lda; secoff = SECB; }
                else              { gp = Bp  + (size_t)r * KDIM; secoff = 2 * SECB; }
            } else {
                if (s2 == 0) { gp = Ahp + (size_t)r * lda; secoff = 0; }
                else         { gp = Bp  + (size_t)r * KDIM; secoff = 2 * SECB; }
            }
            gp += k0 + kq * 8;
            const uint32_t d = db + secoff + (uint32_t)(r * 64 + ((kq * 16) ^ ((r * 8) & 0x30)));
            cp16(d, gp);
        }
    };

    // ldmatrix per-lane addressing (SW64)
    const int a_r  = (lane & 7) + ((lane >> 3) & 1) * 8;
    const int ak2  = ((lane >> 4) & 1) * 16;
    const uint32_t axr = (uint32_t)((a_r << 3) & 0x30);
    const int g    = lane >> 3;
    const int b_r  = ((g >> 1) * 8) + (lane & 7);
    const int bk2  = (g & 1) * 16;
    const uint32_t bxr = (uint32_t)((b_r << 3) & 0x30);

    uint32_t aoff[4], boff[4];
#pragma unroll
    for (int mi = 0; mi < 4; mi++) aoff[mi] = (uint32_t)((wm * 64 + mi * 16 + a_r) * 64);
#pragma unroll
    for (int gi = 0; gi < 4; gi++) boff[gi] = (uint32_t)(2 * SECB + (wn * 64 + gi * 16 + b_r) * 64);

    float acc[4][8][4] = {};

    load_stage(0, 0);
    asm volatile("cp.async.commit_group;\n");
    load_stage(1, 32);
    asm volatile("cp.async.commit_group;\n");
    load_stage(2, 64);
    asm volatile("cp.async.commit_group;\n");

    const int S = KDIM / 32;   // 32
    for (int s = 0; s < S; s++) {
        asm volatile("cp.async.wait_group 2;\n" ::: "memory");
        __syncthreads();
        if (s + 3 < S) load_stage((s + 3) & (STAGES - 1), (s + 3) * 32);
        asm volatile("cp.async.commit_group;\n");

        const uint32_t bb = sbase + (uint32_t)((s & (STAGES - 1)) * STAGEB);
#pragma unroll
        for (int kb = 0; kb < 2; kb++) {
            const uint32_t kx = (uint32_t)(kb * 32);
            uint32_t Bf[4][4];
#pragma unroll
            for (int gi = 0; gi < 4; gi++) {
                const uint32_t ba = bb + boff[gi] + ((kx + bk2) ^ bxr);
                LDSM_X4(Bf[gi][0], Bf[gi][1], Bf[gi][2], Bf[gi][3], ba);
            }
            // hi term
            {
                uint32_t Af[4][4];
#pragma unroll
                for (int mi = 0; mi < 4; mi++) {
                    const uint32_t aa = bb + aoff[mi] + ((kx + ak2) ^ axr);
                    LDSM_X4(Af[mi][0], Af[mi][1], Af[mi][2], Af[mi][3], aa);
                }
#pragma unroll
                for (int gi = 0; gi < 4; gi++)
#pragma unroll
                    for (int mi = 0; mi < 4; mi++)
#pragma unroll
                        for (int hf = 0; hf < 2; hf++)
                            MMA_F16(acc[mi][gi * 2 + hf], Af[mi], Bf[gi][2 * hf], Bf[gi][2 * hf + 1]);
            }
            // lo term
            if (TERMS == 2) {
                uint32_t Af[4][4];
#pragma unroll
                for (int mi = 0; mi < 4; mi++) {
                    const uint32_t aa = bb + aoff[mi] + ((kx + ak2) ^ axr) + SECB;
                    LDSM_X4(Af[mi][0], Af[mi][1], Af[mi][2], Af[mi][3], aa);
                }
#pragma unroll
                for (int gi = 0; gi < 4; gi++)
#pragma unroll
                    for (int mi = 0; mi < 4; mi++)
#pragma unroll
                        for (int hf = 0; hf < 2; hf++)
                            MMA_F16(acc[mi][gi * 2 + hf], Af[mi], Bf[gi][2 * hf], Bf[gi][2 * hf + 1]);
            }
        }
    }

    const int qr = lane >> 2;
    const int qc = (lane & 3) * 2;
    const int seg = blockIdx.x >> 3;   // MODE 1: 1024-col segment (0..6)

    if (MODE == 1 && seg < 2) {
        const float* wn_ = (seg == 0) ? q0 : q1;
#pragma unroll
        for (int mi = 0; mi < 4; mi++)
#pragma unroll
            for (int rh = 0; rh < 2; rh++) {
                float ss = 0.0f;
#pragma unroll
                for (int ti = 0; ti < 8; ti++) {
                    float a = acc[mi][ti][2 * rh], b2 = acc[mi][ti][2 * rh + 1];
                    ss += a * a + b2 * b2;
                }
                ss += __shfl_xor_sync(0xffffffffu, ss, 1);
                ss += __shfl_xor_sync(0xffffffffu, ss, 2);
                const float sc = rsqrtf(ss * (1.0f / 64.0f) + 1e-6f);
#pragma unroll
                for (int ti = 0; ti < 8; ti++) {
                    acc[mi][ti][2 * rh]     *= sc * wn_[ti * 8 + qc];
                    acc[mi][ti][2 * rh + 1] *= sc * wn_[ti * 8 + qc + 1];
                }
            }
    }

#pragma unroll
    for (int mi = 0; mi < 4; mi++) {
#pragma unroll
        for (int ti = 0; ti < 8; ti++) {
            const int col = n0 + wn * 64 + ti * 8 + qc;
            float b0 = 0.f, b1 = 0.f;
            if (MODE == 1 && seg >= 3 && seg <= 5) {
                const float* bp = (seg == 3) ? q2 : (seg == 4) ? q3 : q4;
                const int cs = col & 1023;
                b0 = bp[cs]; b1 = bp[cs + 1];
            }
#pragma unroll
            for (int rh = 0; rh < 2; rh++) {
                const int row = m0 + wm * 64 + mi * 16 + rh * 8 + qr;
                float x0 = acc[mi][ti][2 * rh + 0];
                float x1 = acc[mi][ti][2 * rh + 1];
                if (MODE == 1) {
                    if (seg == 3)                    { x0 = expf(x0 + b0); x1 = expf(x1 + b1); }
                    else if (seg == 4 || seg == 5)   { x0 = 1.0f / (1.0f + expf(-(x0 + b0)));
                                                       x1 = 1.0f / (1.0f + expf(-(x1 + b1))); }
                }
                if (MODE == 0) {
                    *(uint32_t*)&Chh[(size_t)row * ldc + col] = packh(x0, x1);
                } else {
                    *(float2*)&C[(size_t)row * ldc + col] = make_float2(x0, x1);
                }
            }
        }
    }
}

// ---------------------------------------------------------------------------
// Chunk-parallel mLSTM scan (all inputs from pj, ld = 7168)
// ---------------------------------------------------------------------------
__global__ void __launch_bounds__(128, 4)
chunk_fwd(const float* __restrict__ pj,
          float* __restrict__ dC, float* __restrict__ dN, float* __restrict__ G)
{
    __shared__ float stage[2][4][64];

    const int tid = threadIdx.x;
    const int cid = blockIdx.x;
    const int j   = cid & (NCHUNK - 1);
    const int bh  = cid >> 6;
    const int b   = bh >> 4;
    const int h   = bh & 15;
    const size_t base6 = ((size_t)b * LL + (size_t)j * CHUNK) * NPJ + (size_t)h * 64;

    const float* srcs[4] = { pj + base6 + 1024, pj + base6 + 2048,
                             pj + base6 + 3072, pj + base6 + 4096 };
    const int  arr = tid >> 4;
    const int  ch  = tid & 15;
    const bool loader = (tid < 64);
    const float* mySrc = srcs[loader ? arr : 0] + ch * 4;
    const uint32_t mydst0 = (uint32_t)__cvta_generic_to_shared(&stage[0][0][0]) + (arr * 64 + ch * 4) * 4;
    const uint32_t mydst1 = mydst0 + 4 * 64 * 4;

    if (loader) cp16(mydst0, mySrc);
    asm volatile("cp.async.commit_group;\n");

    const int r = tid >> 5;
    const int c = tid & 31;
    float C0[16], C1[16];
#pragma unroll
    for (int i = 0; i < 16; i++) { C0[i] = 0.0f; C1[i] = 0.0f; }
    float nreg = 0.0f, greg = 1.0f;

    for (int t = 0; t < CHUNK; t++) {
        asm volatile("cp.async.wait_group 0;\n" ::: "memory");
        __syncthreads();
        const int cur = t & 1;

        if (t + 1 < CHUNK && loader)
            cp16(cur ? mydst0 : mydst1, mySrc + (size_t)(t + 1) * NPJ);
        asm volatile("cp.async.commit_group;\n");

        const float* S   = &stage[cur][0][0];
        const float* ks  = S;
        const float* vs  = S + 64;
        const float* is_ = S + 128;
        const float* fs  = S + 192;

        float v0 = vs[c], v1 = vs[c + 32];

#pragma unroll
        for (int dd = 0; dd < 16; dd += 4) {
            int d = r * 16 + dd;
            float4 f4 = *(const float4*)&fs[d];
            float4 i4 = *(const float4*)&is_[d];
            float4 k4 = *(const float4*)&ks[d];
            float a0 = i4.x * k4.x, a1 = i4.y * k4.y, a2 = i4.z * k4.z, a3 = i4.w * k4.w;
            C0[dd+0] = fmaf(f4.x, C0[dd+0], a0 * v0); C1[dd+0] = fmaf(f4.x, C1[dd+0], a0 * v1);
            C0[dd+1] = fmaf(f4.y, C0[dd+1], a1 * v0); C1[dd+1] = fmaf(f4.y, C1[dd+1], a1 * v1);
            C0[dd+2] = fmaf(f4.z, C0[dd+2], a2 * v0); C1[dd+2] = fmaf(f4.z, C1[dd+2], a2 * v1);
            C0[dd+3] = fmaf(f4.w, C0[dd+3], a3 * v0); C1[dd+3] = fmaf(f4.w, C1[dd+3], a3 * v1);
        }

        if (tid < 64) {
            float ft = fs[tid];
            nreg = fmaf(ft, nreg, is_[tid] * ks[tid]);
            greg *= ft;
        }
        __syncthreads();
    }

    float* dCp = dC + (size_t)cid * 4096;
#pragma unroll
    for (int dd = 0; dd < 16; dd++) {
        dCp[(r * 16 + dd) * 64 + c]      = C0[dd];
        dCp[(r * 16 + dd) * 64 + c + 32] = C1[dd];
    }
    if (tid < 64) {
        dN[(size_t)cid * 64 + tid] = nreg;
        G [(size_t)cid * 64 + tid] = greg;
    }
}

__global__ void __launch_bounds__(128, 1)
chunk_carry(const float* __restrict__ dC, const float* __restrict__ dN,
            const float* __restrict__ G,
            float* __restrict__ Cst, float* __restrict__ Nst)
{
    __shared__ float gs[64], dns[64];
    const int tid = threadIdx.x;
    const int bh  = blockIdx.x;
    const int r = tid >> 5;
    const int c = tid & 31;

    float C0[16], C1[16];
#pragma unroll
    for (int i = 0; i < 16; i++) { C0[i] = 0.0f; C1[i] = 0.0f; }
    float n = 0.0f;

    for (int j = 0; j < NCHUNK; j++) {
        const size_t cid = (size_t)bh * NCHUNK + j;
        float* Cp = Cst + cid * 4096;
        const float* Dp = dC + cid * 4096;

        if (tid < 64) {
            Nst[cid * 64 + tid] = n;
            gs[tid]  = G [cid * 64 + tid];
            dns[tid] = dN[cid * 64 + tid];
        }
#pragma unroll
        for (int dd = 0; dd < 16; dd++) {
            Cp[(r * 16 + dd) * 64 + c]      = C0[dd];
            Cp[(r * 16 + dd) * 64 + c + 32] = C1[dd];
        }
        __syncthreads();
#pragma unroll
        for (int dd = 0; dd < 16; dd++) {
            float gd = gs[r * 16 + dd];
            C0[dd] = fmaf(gd, C0[dd], Dp[(r * 16 + dd) * 64 + c]);
            C1[dd] = fmaf(gd, C1[dd], Dp[(r * 16 + dd) * 64 + c + 32]);
        }
        if (tid < 64) n = fmaf(gs[tid], n, dns[tid]);
        __syncthreads();
    }
}

__global__ void __launch_bounds__(128, 4)
chunk_out(const float* __restrict__ pj,
          const float* __restrict__ Cst, const float* __restrict__ Nst,
          __half* __restrict__ hh)
{
    __shared__ float stage[2][7][64];
    __shared__ float red[4][64];
    __shared__ float denp[2];

    const int tid = threadIdx.x;
    const int cid = blockIdx.x;
    const int j   = cid & (NCHUNK - 1);
    const int bh  = cid >> 6;
    const int b   = bh >> 4;
    const int h   = bh & 15;
    const size_t base6 = ((size_t)b * LL + (size_t)j * CHUNK) * NPJ + (size_t)h * 64;
    const size_t base1 = ((size_t)b * LL + (size_t)j * CHUNK) * 1024 + (size_t)h * 64;

    // q,k,v,i,f,o,gate at segments 0..6 of pj
    const float* srcs[8] = { pj + base6,        pj + base6 + 1024, pj + base6 + 2048,
                             pj + base6 + 3072, pj + base6 + 4096, pj + base6 + 5120,
                             pj + base6 + 6144, pj + base6 };

    const int  arr = tid >> 4;
    const int  ch  = tid & 15;
    const bool loader = (tid < 112);
    const float* mySrc = srcs[arr] + ch * 4;
    const uint32_t mydst0 = (uint32_t)__cvta_generic_to_shared(&stage[0][0][0]) + (arr * 64 + ch * 4) * 4;
    const uint32_t mydst1 = mydst0 + 7 * 64 * 4;

    if (loader) cp16(mydst0, mySrc);
    asm volatile("cp.async.commit_group;\n");

    const int r = tid >> 5;
    const int c = tid & 31;

    const float* Cp = Cst + (size_t)cid * 4096;
    float C0[16], C1[16];
#pragma unroll
    for (int dd = 0; dd < 16; dd++) {
        C0[dd] = Cp[(r * 16 + dd) * 64 + c];
        C1[dd] = Cp[(r * 16 + dd) * 64 + c + 32];
    }
    float nreg = (tid < 64) ? Nst[(size_t)cid * 64 + tid] : 0.0f;

    for (int t = 0; t < CHUNK; t++) {
        asm volatile("cp.async.wait_group 0;\n" ::: "memory");
        __syncthreads();
        const int cur = t & 1;

        if (t + 1 < CHUNK && loader)
            cp16(cur ? mydst0 : mydst1, mySrc + (size_t)(t + 1) * NPJ);
        asm volatile("cp.async.commit_group;\n");

        const float* S   = &stage[cur][0][0];
        const float* qs  = S;
        const float* ks  = S + 64;
        const float* vs  = S + 128;
        const float* is_ = S + 192;
        const float* fs  = S + 256;
        const float* ogs = S + 320;
        const float* xgs = S + 384;

        float v0 = vs[c], v1 = vs[c + 32];
        float pn0 = 0.0f, pn1 = 0.0f;

#define ROWOP(ff, qq, aa, idx) { float _a = (aa);                              \
        C0[idx] = fmaf((ff), C0[idx], _a * v0); pn0 = fmaf((qq), C0[idx], pn0);\
        C1[idx] = fmaf((ff), C1[idx], _a * v1); pn1 = fmaf((qq), C1[idx], pn1); }

#pragma unroll
        for (int dd = 0; dd < 16; dd += 4) {
            int d = r * 16 + dd;
            float4 f4 = *(const float4*)&fs[d];
            float4 q4 = *(const float4*)&qs[d];
            float4 i4 = *(const float4*)&is_[d];
            float4 k4 = *(const float4*)&ks[d];
            ROWOP(f4.x, q4.x, i4.x * k4.x, dd + 0);
            ROWOP(f4.y, q4.y, i4.y * k4.y, dd + 1);
            ROWOP(f4.z, q4.z, i4.z * k4.z, dd + 2);
            ROWOP(f4.w, q4.w, i4.w * k4.w, dd + 3);
        }
#undef ROWOP

        red[r][c]      = pn0;
        red[r][c + 32] = pn1;

        if (tid < 64) {
            float a = is_[tid] * ks[tid];
            nreg = fmaf(fs[tid], nreg, a);
            float dp = qs[tid] * nreg;
#pragma unroll
            for (int o = 16; o; o >>= 1) dp += __shfl_xor_sync(0xffffffffu, dp, o);
            if ((tid & 31) == 0) denp[tid >> 5] = dp;
        }
        __syncthreads();

        if (tid < 64) {
            float num = red[0][tid] + red[1][tid] + red[2][tid] + red[3][tid];
            float den = fmaxf(denp[0] + denp[1], 1.0f);
            float ov  = (num / den) * ogs[tid] * (1.0f / (1.0f + expf(-xgs[tid])));
            hh[base1 + (size_t)t * 1024 + tid] = __float2half_rn(ov);
        }
    }
}

// ---------------------------------------------------------------------------
// Launch
// ---------------------------------------------------------------------------
extern "C" void kernel_launch(void* const* d_in, const int* in_sizes, int n_in,
                              void* d_out, int out_size)
{
    const float* x     = (const float*)d_in[0];
    const float* w_in  = (const float*)d_in[1];
    const float* w_q   = (const float*)d_in[2];
    const float* w_k   = (const float*)d_in[3];
    const float* w_v   = (const float*)d_in[4];
    const float* w_i   = (const float*)d_in[5];
    const float* b_i   = (const float*)d_in[6];
    const float* w_f   = (const float*)d_in[7];
    const float* b_f   = (const float*)d_in[8];
    const float* w_o   = (const float*)d_in[9];
    const float* b_o   = (const float*)d_in[10];
    const float* w_qn  = (const float*)d_in[11];
    const float* w_kn  = (const float*)d_in[12];
    const float* w_out = (const float*)d_in[13];
    float* out = (float*)d_out;

    float *pj, *dC, *dN, *G, *Cst, *Nst;
    __half *xh, *hh, *wiT, *w6h, *w6l, *wff, *wof;
    cudaGetSymbolAddress((void**)&pj,  g_pj);
    cudaGetSymbolAddress((void**)&dC,  g_dC);
    cudaGetSymbolAddress((void**)&dN,  g_dN);
    cudaGetSymbolAddress((void**)&G,   g_G);
    cudaGetSymbolAddress((void**)&Cst, g_Cst);
    cudaGetSymbolAddress((void**)&Nst, g_Nst);
    cudaGetSymbolAddress((void**)&xh,  g_xh);
    cudaGetSymbolAddress((void**)&hh,  g_hh);
    cudaGetSymbolAddress((void**)&wiT,  g_wiT);
    cudaGetSymbolAddress((void**)&w6h,  g_w6h);
    cudaGetSymbolAddress((void**)&w6l,  g_w6l);
    cudaGetSymbolAddress((void**)&wff,  g_wff);
    cudaGetSymbolAddress((void**)&wof,  g_wof);

    cudaFuncSetAttribute(gemm_f16<0,2>, cudaFuncAttributeMaxDynamicSharedMemorySize, GEMM_SMEM);
    cudaFuncSetAttribute(gemm_f16<1,1>, cudaFuncAttributeMaxDynamicSharedMemorySize, GEMM_SMEM);
    cudaFuncSetAttribute(gemm_f16<2,1>, cudaFuncAttributeMaxDynamicSharedMemorySize, GEMM_SMEM);

    // ---- pass 0: operand conversion ----
    const int NSQ4 = 1024 * 1024 / 4;
    cvt_h<<<(MROWS * 1024 / 4 + 255) / 256, 256>>>((const float4*)x, (uint2*)xh, MROWS * 1024 / 4);
    transpose_wi<<<dim3(32, 32), 256>>>(w_in, wiT);
    // gate weight (w_in rows 1024..2047) -> wff rows 6144..7167 (direct, no Wi multiply)
    cvt_h<<<(NSQ4 + 255) / 256, 256>>>((const float4*)(w_in + (size_t)1024 * 1024),
                                       (uint2*)(wff + (size_t)6144 * 1024), NSQ4);
    split_h6<<<dim3(1024, 6), 256>>>((const float4*)w_q, (const float4*)w_k, (const float4*)w_v,
                                     (const float4*)w_i, (const float4*)w_f, (const float4*)w_o,
                                     (uint2*)w6h, (uint2*)w6l);
    cvt_h<<<(NSQ4 + 255) / 256, 256>>>((const float4*)w_out, (uint2*)wof, NSQ4);

    dim3 blk(128);

    // ---- Wfused[0:6144] = Wproj @ Wi_inner (A = w6 hi/lo, B = WiT) ----
    gemm_f16<0,2><<<dim3(1024 / 128, 6144 / 128), blk, GEMM_SMEM>>>(
        w6h, w6l, 1024, wiT, nullptr, nullptr, nullptr, nullptr, nullptr,
        nullptr, 1024, wff);

    // ---- merged projections + gate, directly from x: pj[8192,7168] ----
    gemm_f16<1,1><<<dim3(NPJ / 128, MROWS / 128), blk, GEMM_SMEM>>>(
        xh, nullptr, 1024, wff, w_qn, w_kn, b_i, b_f, b_o,
        pj, NPJ, nullptr);

    // ---- chunk-parallel scan ----
    chunk_fwd  <<<NCID, 128>>>(pj, dC, dN, G);
    chunk_carry<<<BB * NH, 128>>>(dC, dN, G, Cst, Nst);
    chunk_out  <<<NCID, 128>>>(pj, Cst, Nst, hh);

    // ---- output projection (single-term fp16 A) ----
    gemm_f16<2,1><<<dim3(1024 / 128, MROWS / 128), blk, GEMM_SMEM>>>(
        hh, nullptr, 1024, wof, nullptr, nullptr, nullptr, nullptr, nullptr,
        out, 1024, nullptr);
}

// round 13
// speedup vs baseline: 1.5287x; 1.0878x over previous
#include <cuda_runtime.h>
#include <cuda_fp16.h>
#include <math.h>
#include <stdint.h>

// Problem constants
#define BB   2
#define LL   4096
#define DIMD 1024
#define NH   16
#define HD   64
#define MROWS (BB * LL)          // 8192
#define KDIM 1024
#define CHUNK  64
#define NCHUNK (LL / CHUNK)      // 64
#define NCID   (BB * NH * NCHUNK) // 2048
#define NPJ  7168                // fused projection width: q|k|v|i|f|o|gate

// ---------------------------------------------------------------------------
// Scratch
// ---------------------------------------------------------------------------
__device__ float g_pj[(size_t)MROWS * NPJ];   // q|k|v|i|f|o|xgate, ld=7168
// fp16 operand buffers
__device__ __half g_xh  [(size_t)MROWS * 1024];
__device__ __half g_hh  [(size_t)MROWS * 1024];
__device__ __half g_wiT [(size_t)1024 * 1024];
__device__ __half g_w6h [(size_t)6 * 1024 * 1024];
__device__ __half g_w6l [(size_t)6 * 1024 * 1024];
__device__ __half g_wff [(size_t)NPJ * 1024];
__device__ __half g_wof [(size_t)1024 * 1024];
// chunked-scan scratch
__device__ float g_dC  [(size_t)NCID * 4096];
__device__ float g_dN  [(size_t)NCID * 64];
__device__ float g_G   [(size_t)NCID * 64];
__device__ float g_Cst [(size_t)NCID * 4096];
__device__ float g_Nst [(size_t)NCID * 64];
__device__ float g_numI[(size_t)NCID * 4096];  // intra numerators [cid][t][e]
__device__ float g_qd  [(size_t)NCID * 4096];  // q ⊙ cumdecay     [cid][t][d]
__device__ float g_denI[(size_t)NCID * 64];    // intra denominator [cid][t]

// ---------------------------------------------------------------------------
// helpers
// ---------------------------------------------------------------------------
__device__ __forceinline__ uint32_t packh(float x, float y) {
    __half hx = __float2half_rn(x);
    __half hy = __float2half_rn(y);
    return (uint32_t)__half_as_ushort(hx) | ((uint32_t)__half_as_ushort(hy) << 16);
}
__device__ __forceinline__ uint32_t packhl(float x, float y) {
    __half hx = __float2half_rn(x);
    __half hy = __float2half_rn(y);
    return packh(x - __half2float(hx), y - __half2float(hy));
}
__device__ __forceinline__ void cp16(uint32_t s, const void* g)
{
    asm volatile("cp.async.ca.shared.global [%0], [%1], 16;\n" :: "r"(s), "l"(g));
}

#define LDSM_X4(r0, r1, r2, r3, addr) \
    asm volatile("ldmatrix.sync.aligned.m8n8.x4.shared.b16 {%0,%1,%2,%3}, [%4];" \
                 : "=r"(r0), "=r"(r1), "=r"(r2), "=r"(r3) : "r"(addr))

#define MMA_F16(d, a, b0, b1) \
    asm volatile("mma.sync.aligned.m16n8k16.row.col.f32.f16.f16.f32 " \
                 "{%0,%1,%2,%3}, {%4,%5,%6,%7}, {%8,%9}, {%0,%1,%2,%3};" \
                 : "+f"((d)[0]), "+f"((d)[1]), "+f"((d)[2]), "+f"((d)[3]) \
                 : "r"((a)[0]), "r"((a)[1]), "r"((a)[2]), "r"((a)[3]), \
                   "r"(b0), "r"(b1))

// ---------------------------------------------------------------------------
// Pass 0 kernels
// ---------------------------------------------------------------------------
__global__ void cvt_h(const float4* __restrict__ s, uint2* __restrict__ d, int n4)
{
    int i = blockIdx.x * 256 + threadIdx.x;
    if (i >= n4) return;
    float4 v = s[i];
    uint2 o;
    o.x = packh(v.x, v.y); o.y = packh(v.z, v.w);
    d[i] = o;
}

__global__ void split_h6(const float4* __restrict__ s0, const float4* __restrict__ s1,
                         const float4* __restrict__ s2, const float4* __restrict__ s3,
                         const float4* __restrict__ s4, const float4* __restrict__ s5,
                         uint2* __restrict__ hi, uint2* __restrict__ lo)
{
    const int n4 = 1024 * 1024 / 4;
    int i = blockIdx.x * 256 + threadIdx.x;
    if (i >= n4) return;
    const float4* s;
    switch (blockIdx.y) {
        case 0: s = s0; break; case 1: s = s1; break; case 2: s = s2; break;
        case 3: s = s3; break; case 4: s = s4; break; default: s = s5; break;
    }
    float4 v = s[i];
    uint2 h, l;
    h.x = packh(v.x, v.y);  h.y = packh(v.z, v.w);
    l.x = packhl(v.x, v.y); l.y = packhl(v.z, v.w);
    size_t o = (size_t)blockIdx.y * n4 + i;
    hi[o] = h; lo[o] = l;
}

__global__ void transpose_wi(const float* __restrict__ w, __half* __restrict__ wt)
{
    __shared__ float tile[32][33];
    const int bx = blockIdx.x * 32, by = blockIdx.y * 32;
    const int tx = threadIdx.x & 31, ty = threadIdx.x >> 5;
#pragma unroll
    for (int dy = 0; dy < 32; dy += 8)
        tile[ty + dy][tx] = w[(size_t)(by + ty + dy) * 1024 + bx + tx];
    __syncthreads();
#pragma unroll
    for (int dy = 0; dy < 32; dy += 8)
        wt[(size_t)(bx + ty + dy) * 1024 + by + tx] = __float2half_rn(tile[tx][ty + dy]);
}

// ---------------------------------------------------------------------------
// cp.async pipelined fp16 GEMM (unchanged from R12)
// ---------------------------------------------------------------------------
#define STAGES 4
#define SECB   8192
#define STAGEB (3 * SECB)
#define GEMM_SMEM (STAGES * STAGEB)

template <int MODE, int TERMS>
__global__ void __launch_bounds__(128, 2)
gemm_f16(const __half* __restrict__ Ah, const __half* __restrict__ Al, int lda,
         const __half* __restrict__ B,
         const float* __restrict__ q0, const float* __restrict__ q1,
         const float* __restrict__ q2, const float* __restrict__ q3,
         const float* __restrict__ q4,
         float* __restrict__ C, int ldc,
         __half* __restrict__ Chh)
{
    extern __shared__ __align__(128) char smem[];
    const uint32_t sbase = (uint32_t)__cvta_generic_to_shared(smem);

    const int tid  = threadIdx.x;
    const int w    = tid >> 5;
    const int lane = tid & 31;
    const int wm   = w & 1;
    const int wn   = w >> 1;

    const int m0 = blockIdx.y * 128;
    const int n0 = blockIdx.x * 128;

    const __half* Ahp = Ah + (size_t)m0 * lda;
    const __half* Alp = (TERMS == 2) ? (Al + (size_t)m0 * lda) : nullptr;
    const __half* Bp  = B  + (size_t)n0 * KDIM;

    auto load_stage = [&](int buf, int k0) {
        const uint32_t db = sbase + (uint32_t)(buf * STAGEB);
        const int NCH = (TERMS == 2) ? 12 : 8;
#pragma unroll
        for (int i = 0; i < NCH; i++) {
            const int ci  = tid + i * 128;
            const int s2  = ci >> 9;
            const int r   = (ci >> 2) & 127;
            const int kq  = ci & 3;
            const __half* gp;
            uint32_t secoff;
            if (TERMS == 2) {
                if      (s2 == 0) { gp = Ahp + (size_t)r * lda; secoff = 0; }
                else if (s2 == 1) { gp = Alp + (size_t)r * lda; secoff = SECB; }
                else              { gp = Bp  + (size_t)r * KDIM; secoff = 2 * SECB; }
            } else {
                if (s2 == 0) { gp = Ahp + (size_t)r * lda; secoff = 0; }
                else         { gp = Bp  + (size_t)r * KDIM; secoff = 2 * SECB; }
            }
            gp += k0 + kq * 8;
            const uint32_t d = db + secoff + (uint32_t)(r * 64 + ((kq * 16) ^ ((r * 8) & 0x30)));
            cp16(d, gp);
        }
    };

    const int a_r  = (lane & 7) + ((lane >> 3) & 1) * 8;
    const int ak2  = ((lane >> 4) & 1) * 16;
    const uint32_t axr = (uint32_t)((a_r << 3) & 0x30);
    const int g    = lane >> 3;
    const int b_r  = ((g >> 1) * 8) + (lane & 7);
    const int bk2  = (g & 1) * 16;
    const uint32_t bxr = (uint32_t)((b_r << 3) & 0x30);

    uint32_t aoff[4], boff[4];
#pragma unroll
    for (int mi = 0; mi < 4; mi++) aoff[mi] = (uint32_t)((wm * 64 + mi * 16 + a_r) * 64);
#pragma unroll
    for (int gi = 0; gi < 4; gi++) boff[gi] = (uint32_t)(2 * SECB + (wn * 64 + gi * 16 + b_r) * 64);

    float acc[4][8][4] = {};

    load_stage(0, 0);
    asm volatile("cp.async.commit_group;\n");
    load_stage(1, 32);
    asm volatile("cp.async.commit_group;\n");
    load_stage(2, 64);
    asm volatile("cp.async.commit_group;\n");

    const int S = KDIM / 32;
    for (int s = 0; s < S; s++) {
        asm volatile("cp.async.wait_group 2;\n" ::: "memory");
        __syncthreads();
        if (s + 3 < S) load_stage((s + 3) & (STAGES - 1), (s + 3) * 32);
        asm volatile("cp.async.commit_group;\n");

        const uint32_t bb = sbase + (uint32_t)((s & (STAGES - 1)) * STAGEB);
#pragma unroll
        for (int kb = 0; kb < 2; kb++) {
            const uint32_t kx = (uint32_t)(kb * 32);
            uint32_t Bf[4][4];
#pragma unroll
            for (int gi = 0; gi < 4; gi++) {
                const uint32_t ba = bb + boff[gi] + ((kx + bk2) ^ bxr);
                LDSM_X4(Bf[gi][0], Bf[gi][1], Bf[gi][2], Bf[gi][3], ba);
            }
            {
                uint32_t Af[4][4];
#pragma unroll
                for (int mi = 0; mi < 4; mi++) {
                    const uint32_t aa = bb + aoff[mi] + ((kx + ak2) ^ axr);
                    LDSM_X4(Af[mi][0], Af[mi][1], Af[mi][2], Af[mi][3], aa);
                }
#pragma unroll
                for (int gi = 0; gi < 4; gi++)
#pragma unroll
                    for (int mi = 0; mi < 4; mi++)
#pragma unroll
                        for (int hf = 0; hf < 2; hf++)
                            MMA_F16(acc[mi][gi * 2 + hf], Af[mi], Bf[gi][2 * hf], Bf[gi][2 * hf + 1]);
            }
            if (TERMS == 2) {
                uint32_t Af[4][4];
#pragma unroll
                for (int mi = 0; mi < 4; mi++) {
                    const uint32_t aa = bb + aoff[mi] + ((kx + ak2) ^ axr) + SECB;
                    LDSM_X4(Af[mi][0], Af[mi][1], Af[mi][2], Af[mi][3], aa);
                }
#pragma unroll
                for (int gi = 0; gi < 4; gi++)
#pragma unroll
                    for (int mi = 0; mi < 4; mi++)
#pragma unroll
                        for (int hf = 0; hf < 2; hf++)
                            MMA_F16(acc[mi][gi * 2 + hf], Af[mi], Bf[gi][2 * hf], Bf[gi][2 * hf + 1]);
            }
        }
    }

    const int qr = lane >> 2;
    const int qc = (lane & 3) * 2;
    const int seg = blockIdx.x >> 3;

    if (MODE == 1 && seg < 2) {
        const float* wn_ = (seg == 0) ? q0 : q1;
#pragma unroll
        for (int mi = 0; mi < 4; mi++)
#pragma unroll
            for (int rh = 0; rh < 2; rh++) {
                float ss = 0.0f;
#pragma unroll
                for (int ti = 0; ti < 8; ti++) {
                    float a = acc[mi][ti][2 * rh], b2 = acc[mi][ti][2 * rh + 1];
                    ss += a * a + b2 * b2;
                }
                ss += __shfl_xor_sync(0xffffffffu, ss, 1);
                ss += __shfl_xor_sync(0xffffffffu, ss, 2);
                const float sc = rsqrtf(ss * (1.0f / 64.0f) + 1e-6f);
#pragma unroll
                for (int ti = 0; ti < 8; ti++) {
                    acc[mi][ti][2 * rh]     *= sc * wn_[ti * 8 + qc];
                    acc[mi][ti][2 * rh + 1] *= sc * wn_[ti * 8 + qc + 1];
                }
            }
    }

#pragma unroll
    for (int mi = 0; mi < 4; mi++) {
#pragma unroll
        for (int ti = 0; ti < 8; ti++) {
            const int col = n0 + wn * 64 + ti * 8 + qc;
            float b0 = 0.f, b1 = 0.f;
            if (MODE == 1 && seg >= 3 && seg <= 5) {
                const float* bp = (seg == 3) ? q2 : (seg == 4) ? q3 : q4;
                const int cs = col & 1023;
                b0 = bp[cs]; b1 = bp[cs + 1];
            }
#pragma unroll
            for (int rh = 0; rh < 2; rh++) {
                const int row = m0 + wm * 64 + mi * 16 + rh * 8 + qr;
                float x0 = acc[mi][ti][2 * rh + 0];
                float x1 = acc[mi][ti][2 * rh + 1];
                if (MODE == 1) {
                    if (seg == 3)                  { x0 = expf(x0 + b0); x1 = expf(x1 + b1); }
                    else if (seg == 4 || seg == 5) { x0 = 1.0f / (1.0f + expf(-(x0 + b0)));
                                                     x1 = 1.0f / (1.0f + expf(-(x1 + b1))); }
                }
                if (MODE == 0) {
                    *(uint32_t*)&Chh[(size_t)row * ldc + col] = packh(x0, x1);
                } else {
                    *(float2*)&C[(size_t)row * ldc + col] = make_float2(x0, x1);
                }
            }
        }
    }
}

// ---------------------------------------------------------------------------
// Scan pass A: single zero-state recurrence; emits per-step intra numerators,
// intra denominator, qd = q ⊙ cumdecay; and ΔC, Δn, G at chunk end.
// ---------------------------------------------------------------------------
__global__ void __launch_bounds__(128, 4)
chunk_fwdA(const float* __restrict__ pj,
           float* __restrict__ dC, float* __restrict__ dN, float* __restrict__ G,
           float* __restrict__ numI, float* __restrict__ qd, float* __restrict__ denI)
{
    __shared__ float stage[2][5][64];
    __shared__ float red[4][64];
    __shared__ float denp[2];

    const int tid = threadIdx.x;
    const int cid = blockIdx.x;
    const int j   = cid & (NCHUNK - 1);
    const int bh  = cid >> 6;
    const int b   = bh >> 4;
    const int h   = bh & 15;
    const size_t base6 = ((size_t)b * LL + (size_t)j * CHUNK) * NPJ + (size_t)h * 64;

    // q,k,v,i,f at segments 0..4
    const float* srcs[5] = { pj + base6,        pj + base6 + 1024, pj + base6 + 2048,
                             pj + base6 + 3072, pj + base6 + 4096 };

    const int  arr = tid >> 4;
    const int  ch  = tid & 15;
    const bool loader = (tid < 80);
    const float* mySrc = srcs[loader ? arr : 0] + ch * 4;
    const uint32_t mydst0 = (uint32_t)__cvta_generic_to_shared(&stage[0][0][0]) + (arr * 64 + ch * 4) * 4;
    const uint32_t mydst1 = mydst0 + 5 * 64 * 4;

    if (loader) cp16(mydst0, mySrc);
    asm volatile("cp.async.commit_group;\n");

    const int r = tid >> 5;
    const int c = tid & 31;
    float C0[16], C1[16];
#pragma unroll
    for (int i = 0; i < 16; i++) { C0[i] = 0.0f; C1[i] = 0.0f; }
    float nreg = 0.0f, cum = 1.0f;

    float* numIp = numI + (size_t)cid * 4096;
    float* qdp   = qd   + (size_t)cid * 4096;
    float* denIp = denI + (size_t)cid * 64;

    for (int t = 0; t < CHUNK; t++) {
        asm volatile("cp.async.wait_group 0;\n" ::: "memory");
        __syncthreads();
        const int cur = t & 1;

        if (t + 1 < CHUNK && loader)
            cp16(cur ? mydst0 : mydst1, mySrc + (size_t)(t + 1) * NPJ);
        asm volatile("cp.async.commit_group;\n");

        const float* S   = &stage[cur][0][0];
        const float* qs  = S;
        const float* ks  = S + 64;
        const float* vs  = S + 128;
        const float* is_ = S + 192;
        const float* fs  = S + 256;

        float v0 = vs[c], v1 = vs[c + 32];
        float pn0 = 0.0f, pn1 = 0.0f;

#define ROWOP(ff, qq, aa, idx) { float _a = (aa);                              \
        C0[idx] = fmaf((ff), C0[idx], _a * v0); pn0 = fmaf((qq), C0[idx], pn0);\
        C1[idx] = fmaf((ff), C1[idx], _a * v1); pn1 = fmaf((qq), C1[idx], pn1); }

#pragma unroll
        for (int dd = 0; dd < 16; dd += 4) {
            int d = r * 16 + dd;
            float4 f4 = *(const float4*)&fs[d];
            float4 q4 = *(const float4*)&qs[d];
            float4 i4 = *(const float4*)&is_[d];
            float4 k4 = *(const float4*)&ks[d];
            ROWOP(f4.x, q4.x, i4.x * k4.x, dd + 0);
            ROWOP(f4.y, q4.y, i4.y * k4.y, dd + 1);
            ROWOP(f4.z, q4.z, i4.z * k4.z, dd + 2);
            ROWOP(f4.w, q4.w, i4.w * k4.w, dd + 3);
        }
#undef ROWOP

        red[r][c]      = pn0;
        red[r][c + 32] = pn1;

        float qdv = 0.0f;
        if (tid < 64) {
            float a = is_[tid] * ks[tid];
            nreg = fmaf(fs[tid], nreg, a);
            cum *= fs[tid];
            qdv = qs[tid] * cum;
            float dp = qs[tid] * nreg;
#pragma unroll
            for (int o = 16; o; o >>= 1) dp += __shfl_xor_sync(0xffffffffu, dp, o);
            if ((tid & 31) == 0) denp[tid >> 5] = dp;
        }
        __syncthreads();

        if (tid < 64) {
            float num = red[0][tid] + red[1][tid] + red[2][tid] + red[3][tid];
            numIp[t * 64 + tid] = num;
            qdp[t * 64 + tid]   = qdv;
            if (tid == 0) denIp[t] = denp[0] + denp[1];
        }
    }

    float* dCp = dC + (size_t)cid * 4096;
#pragma unroll
    for (int dd = 0; dd < 16; dd++) {
        dCp[(r * 16 + dd) * 64 + c]      = C0[dd];
        dCp[(r * 16 + dd) * 64 + c + 32] = C1[dd];
    }
    if (tid < 64) {
        dN[(size_t)cid * 64 + tid] = nreg;
        G [(size_t)cid * 64 + tid] = cum;
    }
}

// ---------------------------------------------------------------------------
// Parallel carry: recurrence across chunks, independent per state element.
// grid (32 bh, 9): y<8 -> 512 C-elements each; y==8 -> n (64 elems).
// ---------------------------------------------------------------------------
__global__ void __launch_bounds__(128)
chunk_carryP(const float* __restrict__ dC, const float* __restrict__ dN,
             const float* __restrict__ G,
             float* __restrict__ Cst, float* __restrict__ Nst)
{
    const int bh  = blockIdx.x;
    const int y   = blockIdx.y;
    const int tid = threadIdx.x;

    if (y < 8) {
        const int el = y * 512 + tid * 4;
        const int d  = el >> 6;
        float4 Cv = make_float4(0.f, 0.f, 0.f, 0.f);
        for (int j = 0; j < NCHUNK; j++) {
            const size_t cid = (size_t)bh * NCHUNK + j;
            *(float4*)&Cst[cid * 4096 + el] = Cv;
            const float g = G[cid * 64 + d];
            float4 dv = *(const float4*)&dC[cid * 4096 + el];
            Cv.x = fmaf(g, Cv.x, dv.x);
            Cv.y = fmaf(g, Cv.y, dv.y);
            Cv.z = fmaf(g, Cv.z, dv.z);
            Cv.w = fmaf(g, Cv.w, dv.w);
        }
    } else if (tid < 16) {
        const int e = tid * 4;
        float4 nv = make_float4(0.f, 0.f, 0.f, 0.f);
        for (int j = 0; j < NCHUNK; j++) {
            const size_t cid = (size_t)bh * NCHUNK + j;
            *(float4*)&Nst[cid * 64 + e] = nv;
            float4 gv = *(const float4*)&G[cid * 64 + e];
            float4 dn = *(const float4*)&dN[cid * 64 + e];
            nv.x = fmaf(gv.x, nv.x, dn.x);
            nv.y = fmaf(gv.y, nv.y, dn.y);
            nv.z = fmaf(gv.z, nv.z, dn.z);
            nv.w = fmaf(gv.w, nv.w, dn.w);
        }
    }
}

// ---------------------------------------------------------------------------
// Scan pass B: inter correction + output.
// num = numI + qd @ C_start ; den = max(denI + qd·n_start, 1)
// out = num/den * og * sigmoid(gate)  -> fp16
// ---------------------------------------------------------------------------
__global__ void __launch_bounds__(128)
chunk_inter(const float* __restrict__ pj,
            const float* __restrict__ Cst, const float* __restrict__ Nst,
            const float* __restrict__ numI, const float* __restrict__ qd,
            const float* __restrict__ denI,
            __half* __restrict__ hh)
{
    __shared__ float qs_[64 * 65];   // qd, rows padded (column reads)
    __shared__ float cs_[64 * 64];   // C_start (row reads)
    __shared__ float ns_[64], den_[64], dI_[64];

    const int tid = threadIdx.x;
    const int cid = blockIdx.x;
    const int j   = cid & (NCHUNK - 1);
    const int bh  = cid >> 6;
    const int b   = bh >> 4;
    const int h   = bh & 15;
    const size_t row0 = (size_t)b * LL + (size_t)j * CHUNK;   // global row of t=0

    // cooperative loads
#pragma unroll
    for (int i = 0; i < 8; i++) {
        const int lin = tid + i * 128;        // 1024 float4 groups
        const int t   = lin >> 4;
        const int dg  = (lin & 15) * 4;
        float4 qv = *(const float4*)&qd [(size_t)cid * 4096 + t * 64 + dg];
        qs_[t * 65 + dg + 0] = qv.x; qs_[t * 65 + dg + 1] = qv.y;
        qs_[t * 65 + dg + 2] = qv.z; qs_[t * 65 + dg + 3] = qv.w;
        *(float4*)&cs_[t * 64 + dg] = *(const float4*)&Cst[(size_t)cid * 4096 + t * 64 + dg];
    }
    if (tid < 64) {
        ns_[tid] = Nst [(size_t)cid * 64 + tid];
        dI_[tid] = denI[(size_t)cid * 64 + tid];
    }
    __syncthreads();

    if (tid < 64) {
        float s = dI_[tid];
#pragma unroll 8
        for (int d = 0; d < 64; d++) s = fmaf(qs_[tid * 65 + d], ns_[d], s);
        den_[tid] = fmaxf(s, 1.0f);
    }
    __syncthreads();

    // register-tiled 4t x 8e per thread
    const int tg = tid >> 3;          // 0..15
    const int eg = tid & 7;           // 0..7
    const int t0 = tg * 4;
    const int e0 = eg * 8;

    float acc[4][8];
#pragma unroll
    for (int a = 0; a < 4; a++) {
        float4 u0 = *(const float4*)&numI[(size_t)cid * 4096 + (t0 + a) * 64 + e0];
        float4 u1 = *(const float4*)&numI[(size_t)cid * 4096 + (t0 + a) * 64 + e0 + 4];
        acc[a][0] = u0.x; acc[a][1] = u0.y; acc[a][2] = u0.z; acc[a][3] = u0.w;
        acc[a][4] = u1.x; acc[a][5] = u1.y; acc[a][6] = u1.z; acc[a][7] = u1.w;
    }

#pragma unroll 4
    for (int d = 0; d < 64; d++) {
        float q0 = qs_[(t0 + 0) * 65 + d];
        float q1 = qs_[(t0 + 1) * 65 + d];
        float q2 = qs_[(t0 + 2) * 65 + d];
        float q3 = qs_[(t0 + 3) * 65 + d];
        float4 c0 = *(const float4*)&cs_[d * 64 + e0];
        float4 c1 = *(const float4*)&cs_[d * 64 + e0 + 4];
        float cv[8] = { c0.x, c0.y, c0.z, c0.w, c1.x, c1.y, c1.z, c1.w };
#pragma unroll
        for (int bb2 = 0; bb2 < 8; bb2++) {
            acc[0][bb2] = fmaf(q0, cv[bb2], acc[0][bb2]);
            acc[1][bb2] = fmaf(q1, cv[bb2], acc[1][bb2]);
            acc[2][bb2] = fmaf(q2, cv[bb2], acc[2][bb2]);
            acc[3][bb2] = fmaf(q3, cv[bb2], acc[3][bb2]);
        }
    }

    // epilogue: og * sigmoid(gate) * num/den -> fp16
#pragma unroll
    for (int a = 0; a < 4; a++) {
        const size_t grow = row0 + t0 + a;
        const size_t pb = grow * NPJ + (size_t)h * 64 + e0;
        float4 og0 = *(const float4*)&pj[pb + 5120];
        float4 og1 = *(const float4*)&pj[pb + 5124];
        float4 gt0 = *(const float4*)&pj[pb + 6144];
        float4 gt1 = *(const float4*)&pj[pb + 6148];
        float ogv[8] = { og0.x, og0.y, og0.z, og0.w, og1.x, og1.y, og1.z, og1.w };
        float gtv[8] = { gt0.x, gt0.y, gt0.z, gt0.w, gt1.x, gt1.y, gt1.z, gt1.w };
        const float dinv = 1.0f / den_[t0 + a];
        uint32_t packed[4];
#pragma unroll
        for (int p = 0; p < 4; p++) {
            float o0 = (acc[a][2*p]   * dinv) * ogv[2*p]   * (1.0f / (1.0f + expf(-gtv[2*p])));
            float o1 = (acc[a][2*p+1] * dinv) * ogv[2*p+1] * (1.0f / (1.0f + expf(-gtv[2*p+1])));
            packed[p] = packh(o0, o1);
        }
        *(uint4*)&hh[grow * 1024 + (size_t)h * 64 + e0] =
            make_uint4(packed[0], packed[1], packed[2], packed[3]);
    }
}

// ---------------------------------------------------------------------------
// Launch
// ---------------------------------------------------------------------------
extern "C" void kernel_launch(void* const* d_in, const int* in_sizes, int n_in,
                              void* d_out, int out_size)
{
    const float* x     = (const float*)d_in[0];
    const float* w_in  = (const float*)d_in[1];
    const float* w_q   = (const float*)d_in[2];
    const float* w_k   = (const float*)d_in[3];
    const float* w_v   = (const float*)d_in[4];
    const float* w_i   = (const float*)d_in[5];
    const float* b_i   = (const float*)d_in[6];
    const float* w_f   = (const float*)d_in[7];
    const float* b_f   = (const float*)d_in[8];
    const float* w_o   = (const float*)d_in[9];
    const float* b_o   = (const float*)d_in[10];
    const float* w_qn  = (const float*)d_in[11];
    const float* w_kn  = (const float*)d_in[12];
    const float* w_out = (const float*)d_in[13];
    float* out = (float*)d_out;

    float *pj, *dC, *dN, *G, *Cst, *Nst, *numI, *qdb, *denI;
    __half *xh, *hh, *wiT, *w6h, *w6l, *wff, *wof;
    cudaGetSymbolAddress((void**)&pj,   g_pj);
    cudaGetSymbolAddress((void**)&dC,   g_dC);
    cudaGetSymbolAddress((void**)&dN,   g_dN);
    cudaGetSymbolAddress((void**)&G,    g_G);
    cudaGetSymbolAddress((void**)&Cst,  g_Cst);
    cudaGetSymbolAddress((void**)&Nst,  g_Nst);
    cudaGetSymbolAddress((void**)&numI, g_numI);
    cudaGetSymbolAddress((void**)&qdb,  g_qd);
    cudaGetSymbolAddress((void**)&denI, g_denI);
    cudaGetSymbolAddress((void**)&xh,   g_xh);
    cudaGetSymbolAddress((void**)&hh,   g_hh);
    cudaGetSymbolAddress((void**)&wiT,  g_wiT);
    cudaGetSymbolAddress((void**)&w6h,  g_w6h);
    cudaGetSymbolAddress((void**)&w6l,  g_w6l);
    cudaGetSymbolAddress((void**)&wff,  g_wff);
    cudaGetSymbolAddress((void**)&wof,  g_wof);

    cudaFuncSetAttribute(gemm_f16<0,2>, cudaFuncAttributeMaxDynamicSharedMemorySize, GEMM_SMEM);
    cudaFuncSetAttribute(gemm_f16<1,1>, cudaFuncAttributeMaxDynamicSharedMemorySize, GEMM_SMEM);
    cudaFuncSetAttribute(gemm_f16<2,1>, cudaFuncAttributeMaxDynamicSharedMemorySize, GEMM_SMEM);

    // ---- pass 0: operand conversion ----
    const int NSQ4 = 1024 * 1024 / 4;
    cvt_h<<<(MROWS * 1024 / 4 + 255) / 256, 256>>>((const float4*)x, (uint2*)xh, MROWS * 1024 / 4);
    transpose_wi<<<dim3(32, 32), 256>>>(w_in, wiT);
    cvt_h<<<(NSQ4 + 255) / 256, 256>>>((const float4*)(w_in + (size_t)1024 * 1024),
                                       (uint2*)(wff + (size_t)6144 * 1024), NSQ4);
    split_h6<<<dim3(1024, 6), 256>>>((const float4*)w_q, (const float4*)w_k, (const float4*)w_v,
                                     (const float4*)w_i, (const float4*)w_f, (const float4*)w_o,
                                     (uint2*)w6h, (uint2*)w6l);
    cvt_h<<<(NSQ4 + 255) / 256, 256>>>((const float4*)w_out, (uint2*)wof, NSQ4);

    dim3 blk(128);

    // ---- Wfused[0:6144] = Wproj @ Wi_inner ----
    gemm_f16<0,2><<<dim3(1024 / 128, 6144 / 128), blk, GEMM_SMEM>>>(
        w6h, w6l, 1024, wiT, nullptr, nullptr, nullptr, nullptr, nullptr,
        nullptr, 1024, wff);

    // ---- merged projections + gate from x: pj[8192,7168] ----
    gemm_f16<1,1><<<dim3(NPJ / 128, MROWS / 128), blk, GEMM_SMEM>>>(
        xh, nullptr, 1024, wff, w_qn, w_kn, b_i, b_f, b_o,
        pj, NPJ, nullptr);

    // ---- chunk-parallel scan: A (single recurrence) -> carry -> B ----
    chunk_fwdA  <<<NCID, 128>>>(pj, dC, dN, G, numI, qdb, denI);
    chunk_carryP<<<dim3(BB * NH, 9), 128>>>(dC, dN, G, Cst, Nst);
    chunk_inter <<<NCID, 128>>>(pj, Cst, Nst, numI, qdb, denI, hh);

    // ---- output projection (single-term fp16 A) ----
    gemm_f16<2,1><<<dim3(1024 / 128, MROWS / 128), blk, GEMM_SMEM>>>(
        hh, nullptr, 1024, wof, nullptr, nullptr, nullptr, nullptr, nullptr,
        out, 1024, nullptr);
}